// round 2
// baseline (speedup 1.0000x reference)
#include <cuda_runtime.h>

#define BB 2
#define SS 2048
#define HH 1024
#define NH 16
#define H3 3072
#define NROWS (BB*SS)   // 4096

// ------------------------ scratch (__device__ globals; no allocation) ---------
__device__ float g_q[NROWS*HH];
__device__ float g_k[NROWS*HH];
__device__ float g_v[NROWS*HH];
__device__ float g_ctx[NROWS*HH];
__device__ float g_bctx[NROWS*HH];
__device__ float g_qkv[NROWS*H3];
__device__ float g_mod[NROWS*NH];
__device__ float g_aw[NH];

// ------------------------ awareness: aw[h] = ba[h] + cvec @ Wa ----------------
__global__ void awareness_kernel(const float* __restrict__ cv,
                                 const float* __restrict__ Wa,
                                 const float* __restrict__ ba,
                                 float* __restrict__ aw) {
    int h = threadIdx.x;
    if (h < NH) {
        float s = ba[h];
#pragma unroll
        for (int c = 0; c < 16; c++) s += cv[c] * Wa[c*NH + h];
        aw[h] = s;
    }
}

// ------------------------ modulation: sigmoid(X@Wg + bg + aw) -----------------
__global__ __launch_bounds__(256) void modulation_kernel(
    const float* __restrict__ X, const float* __restrict__ Wg,
    const float* __restrict__ bg, const float* __restrict__ aw,
    float* __restrict__ modv) {
    int gid = blockIdx.x * 256 + threadIdx.x;   // row*NH + h
    int row = gid >> 4, h = gid & 15;
    const float* x = X + (size_t)row * HH;
    float s = 0.f;
#pragma unroll 8
    for (int k = 0; k < HH; k++) s += x[k] * Wg[k*NH + h];
    s += bg[h] + aw[h];
    modv[gid] = 1.f / (1.f + __expf(-s));
}

// ------------------------ fp32 SGEMM: C = alpha*(A@W + bias) + beta*Cold ------
// A: [M,K] row-major, W: [K,N] row-major. 128x128x8 tile, 256 thr, 8x8/thread.
__global__ __launch_bounds__(256) void sgemm(
    const float* __restrict__ A, const float* __restrict__ W,
    const float* __restrict__ bias, const float* __restrict__ Cold,
    float* __restrict__ C, int M, int N, int K, float alpha, float beta)
{
    __shared__ float As[8][132];
    __shared__ float Bs[8][132];
    const int tid = threadIdx.x;
    const int tx = tid & 15, ty = tid >> 4;
    const int mbase = blockIdx.y * 128, nbase = blockIdx.x * 128;

    float acc[8][8];
#pragma unroll
    for (int i = 0; i < 8; i++)
#pragma unroll
        for (int j = 0; j < 8; j++) acc[i][j] = 0.f;

    const int arow = tid >> 1, acol = (tid & 1) * 4;
    const int brow = tid >> 5, bcol = (tid & 31) * 4;
    const float* Aptr = A + (size_t)(mbase + arow) * K + acol;
    const float* Bptr = W + (size_t)brow * N + nbase + bcol;

    for (int k0 = 0; k0 < K; k0 += 8) {
        float4 av = *(const float4*)(Aptr + k0);
        float4 bv = *(const float4*)(Bptr + (size_t)k0 * N);
        As[acol+0][arow] = av.x;
        As[acol+1][arow] = av.y;
        As[acol+2][arow] = av.z;
        As[acol+3][arow] = av.w;
        *(float4*)&Bs[brow][bcol] = bv;
        __syncthreads();
#pragma unroll
        for (int kk = 0; kk < 8; kk++) {
            float4 a0 = *(const float4*)&As[kk][ty*4];
            float4 a1 = *(const float4*)&As[kk][64 + ty*4];
            float4 b0 = *(const float4*)&Bs[kk][tx*4];
            float4 b1 = *(const float4*)&Bs[kk][64 + tx*4];
            float ar[8] = {a0.x,a0.y,a0.z,a0.w,a1.x,a1.y,a1.z,a1.w};
            float br[8] = {b0.x,b0.y,b0.z,b0.w,b1.x,b1.y,b1.z,b1.w};
#pragma unroll
            for (int i = 0; i < 8; i++)
#pragma unroll
                for (int j = 0; j < 8; j++)
                    acc[i][j] += ar[i] * br[j];
        }
        __syncthreads();
    }

#pragma unroll
    for (int i = 0; i < 8; i++) {
        int row = mbase + ((i < 4) ? (ty*4 + i) : (64 + ty*4 + (i-4)));
#pragma unroll
        for (int jj = 0; jj < 2; jj++) {
            int col = nbase + ((jj == 0) ? tx*4 : (64 + tx*4));
            float4 o;
            o.x = alpha * (acc[i][jj*4+0] + bias[col+0]);
            o.y = alpha * (acc[i][jj*4+1] + bias[col+1]);
            o.z = alpha * (acc[i][jj*4+2] + bias[col+2]);
            o.w = alpha * (acc[i][jj*4+3] + bias[col+3]);
            if (beta != 0.f) {
                float4 old = *(const float4*)(Cold + (size_t)row*N + col);
                o.x += beta*old.x; o.y += beta*old.y;
                o.z += beta*old.z; o.w += beta*old.w;
            }
            *(float4*)(C + (size_t)row*N + col) = o;
        }
    }
}

// ------------------------ flash attention, main (16 heads, hd=64) -------------
// grid (S/64, NH, B), 256 threads as 16x16. Online softmax. Per-row modulation
// scale on scores; key mask -> -1e30 before softmax.
__global__ __launch_bounds__(256) void flash_main(
    const float* __restrict__ Q, const float* __restrict__ K,
    const float* __restrict__ V, const float* __restrict__ modv,
    const int* __restrict__ mask, float* __restrict__ O)
{
    extern __shared__ float sm[];
    float* Qs = sm;              // [64 d][68] (d-major, m inner)
    float* Ks = sm + 64*68;      // [64 d][68] (d-major, n inner)
    float* Vs = sm + 2*64*68;    // [64 n][68] (n-major, d inner)
    float* Ps = sm + 3*64*68;    // [64 m][68] (m-major, n inner)
    const int tid = threadIdx.x;
    const int tx = tid & 15, ty = tid >> 4;
    const int qt = blockIdx.x, h = blockIdx.y, b = blockIdx.z;
    const int qrow0 = b*SS + qt*64;

    const float* qg = Q + (size_t)qrow0 * HH + h*64;
#pragma unroll
    for (int i = 0; i < 16; i++) {
        int idx = tid + i*256;
        int m = idx >> 6, d = idx & 63;
        Qs[d*68 + m] = qg[(size_t)m*HH + d];
    }

    float mrow[4];
#pragma unroll
    for (int i = 0; i < 4; i++)
        mrow[i] = modv[(size_t)(qrow0 + ty*4 + i)*NH + h] * 0.125f; // 1/sqrt(64)

    float oacc[4][4];
#pragma unroll
    for (int i = 0; i < 4; i++)
#pragma unroll
        for (int j = 0; j < 4; j++) oacc[i][j] = 0.f;
    float mrun[4], lrun[4];
#pragma unroll
    for (int i = 0; i < 4; i++) { mrun[i] = -1e30f; lrun[i] = 0.f; }

    for (int kt = 0; kt < SS/64; kt++) {
        const int krow0 = b*SS + kt*64;
        const float* kg = K + (size_t)krow0*HH + h*64;
        const float* vg = V + (size_t)krow0*HH + h*64;
        __syncthreads();   // previous tile's smem fully consumed
#pragma unroll
        for (int i = 0; i < 16; i++) {
            int idx = tid + i*256;
            int n = idx >> 6, d = idx & 63;
            Ks[d*68 + n] = kg[(size_t)n*HH + d];
            Vs[n*68 + d] = vg[(size_t)n*HH + d];
        }
        __syncthreads();

        float sacc[4][4];
#pragma unroll
        for (int i = 0; i < 4; i++)
#pragma unroll
            for (int j = 0; j < 4; j++) sacc[i][j] = 0.f;
#pragma unroll 8
        for (int d = 0; d < 64; d++) {
            float4 qv = *(const float4*)&Qs[d*68 + ty*4];
            float4 kv = *(const float4*)&Ks[d*68 + tx*4];
            float qa[4] = {qv.x,qv.y,qv.z,qv.w};
            float ka[4] = {kv.x,kv.y,kv.z,kv.w};
#pragma unroll
            for (int i = 0; i < 4; i++)
#pragma unroll
                for (int j = 0; j < 4; j++)
                    sacc[i][j] += qa[i]*ka[j];
        }

        float mk[4];
#pragma unroll
        for (int j = 0; j < 4; j++)
            mk[j] = mask[krow0 + tx*4 + j] ? 0.f : -1e30f;

#pragma unroll
        for (int i = 0; i < 4; i++) {
            float srow[4], rmax = -1e30f;
#pragma unroll
            for (int j = 0; j < 4; j++) {
                srow[j] = sacc[i][j]*mrow[i] + mk[j];
                rmax = fmaxf(rmax, srow[j]);
            }
#pragma unroll
            for (int off = 1; off < 16; off <<= 1)
                rmax = fmaxf(rmax, __shfl_xor_sync(0xffffffffu, rmax, off));
            float mnew = fmaxf(mrun[i], rmax);
            float corr = __expf(mrun[i] - mnew);
            float p[4]; float ls = 0.f;
#pragma unroll
            for (int j = 0; j < 4; j++) { p[j] = __expf(srow[j] - mnew); ls += p[j]; }
#pragma unroll
            for (int off = 1; off < 16; off <<= 1)
                ls += __shfl_xor_sync(0xffffffffu, ls, off);
            lrun[i] = lrun[i]*corr + ls;
            mrun[i] = mnew;
#pragma unroll
            for (int j = 0; j < 4; j++) oacc[i][j] *= corr;
            *(float4*)&Ps[(ty*4+i)*68 + tx*4] = make_float4(p[0],p[1],p[2],p[3]);
        }
        __syncthreads();

#pragma unroll 8
        for (int n = 0; n < 64; n++) {
            float4 vv = *(const float4*)&Vs[n*68 + tx*4];
#pragma unroll
            for (int i = 0; i < 4; i++) {
                float p = Ps[(ty*4+i)*68 + n];
                oacc[i][0] += p*vv.x; oacc[i][1] += p*vv.y;
                oacc[i][2] += p*vv.z; oacc[i][3] += p*vv.w;
            }
        }
    }

    float* og = O + (size_t)qrow0*HH + h*64;
#pragma unroll
    for (int i = 0; i < 4; i++) {
        float linv = 1.f / lrun[i];
        *(float4*)&og[(size_t)(ty*4+i)*HH + tx*4] =
            make_float4(oacc[i][0]*linv, oacc[i][1]*linv,
                        oacc[i][2]*linv, oacc[i][3]*linv);
    }
}

// ------------------------ flash attention, branch MHA (4 heads, hd=256) -------
// q/k/v packed in QKV[row][3H] at offsets h*256 / 1024+h*256 / 2048+h*256.
// grid (S/64, 4, B), 256 threads. Scores: 16x16 thread grid (4x4/thread) over
// 4 d-chunks of 64. O phase: warp-per-8-rows, lane owns d = lane*4 (+128).
__global__ __launch_bounds__(256, 1) void flash_branch(
    const float* __restrict__ QKV, float* __restrict__ O, float scale)
{
    extern __shared__ float sm[];
    float* Qs   = sm;                  // [256 d][68]
    float* Ks   = Qs + 256*68;         // [64 d][68]
    float* Vs   = Ks + 64*68;          // [64 n][260]
    float* Ps   = Vs + 64*260;         // [64 m][68]
    float* rstat= Ps + 64*68;          // [64] row corr / 1/l
    const int tid = threadIdx.x;
    const int tx = tid & 15, ty = tid >> 4;
    const int lane = tid & 31, wrp = tid >> 5;
    const int m0 = wrp * 8;
    const int qt = blockIdx.x, h = blockIdx.y, b = blockIdx.z;
    const int qrow0 = b*SS + qt*64;

    const float* qg = QKV + (size_t)qrow0*H3 + h*256;
#pragma unroll 4
    for (int i = 0; i < 64; i++) {
        int idx = tid + i*256;
        int m = idx >> 8, d = idx & 255;
        Qs[d*68 + m] = qg[(size_t)m*H3 + d];
    }

    float oacc[8][8];
#pragma unroll
    for (int r = 0; r < 8; r++)
#pragma unroll
        for (int c = 0; c < 8; c++) oacc[r][c] = 0.f;
    float mrun[4], lrun[4];
#pragma unroll
    for (int i = 0; i < 4; i++) { mrun[i] = -1e30f; lrun[i] = 0.f; }

    for (int kt = 0; kt < SS/64; kt++) {
        const int krow0 = b*SS + kt*64;
        const float* kg = QKV + (size_t)krow0*H3 + HH   + h*256;
        const float* vg = QKV + (size_t)krow0*H3 + 2*HH + h*256;
        __syncthreads();   // prev tile's Vs/Ps/rstat consumed
#pragma unroll 4
        for (int i = 0; i < 64; i++) {
            int idx = tid + i*256;
            int n = idx >> 8, d = idx & 255;
            Vs[n*260 + d] = vg[(size_t)n*H3 + d];
        }

        float sacc[4][4];
#pragma unroll
        for (int i = 0; i < 4; i++)
#pragma unroll
            for (int j = 0; j < 4; j++) sacc[i][j] = 0.f;

        for (int dc = 0; dc < 4; dc++) {
            __syncthreads();   // Ks free
#pragma unroll
            for (int i = 0; i < 16; i++) {
                int idx = tid + i*256;
                int n = idx >> 6, d = idx & 63;
                Ks[d*68 + n] = kg[(size_t)n*H3 + dc*64 + d];
            }
            __syncthreads();
#pragma unroll 8
            for (int d = 0; d < 64; d++) {
                float4 qv = *(const float4*)&Qs[(dc*64 + d)*68 + ty*4];
                float4 kv = *(const float4*)&Ks[d*68 + tx*4];
                float qa[4] = {qv.x,qv.y,qv.z,qv.w};
                float ka[4] = {kv.x,kv.y,kv.z,kv.w};
#pragma unroll
                for (int i = 0; i < 4; i++)
#pragma unroll
                    for (int j = 0; j < 4; j++)
                        sacc[i][j] += qa[i]*ka[j];
            }
        }

#pragma unroll
        for (int i = 0; i < 4; i++) {
            float srow[4], rmax = -1e30f;
#pragma unroll
            for (int j = 0; j < 4; j++) {
                srow[j] = sacc[i][j] * scale;
                rmax = fmaxf(rmax, srow[j]);
            }
#pragma unroll
            for (int off = 1; off < 16; off <<= 1)
                rmax = fmaxf(rmax, __shfl_xor_sync(0xffffffffu, rmax, off));
            float mnew = fmaxf(mrun[i], rmax);
            float corr = __expf(mrun[i] - mnew);
            float p[4]; float ls = 0.f;
#pragma unroll
            for (int j = 0; j < 4; j++) { p[j] = __expf(srow[j] - mnew); ls += p[j]; }
#pragma unroll
            for (int off = 1; off < 16; off <<= 1)
                ls += __shfl_xor_sync(0xffffffffu, ls, off);
            lrun[i] = lrun[i]*corr + ls;
            mrun[i] = mnew;
            if (tx == 0) rstat[ty*4 + i] = corr;
            *(float4*)&Ps[(ty*4+i)*68 + tx*4] = make_float4(p[0],p[1],p[2],p[3]);
        }
        __syncthreads();

        float cf[8];
#pragma unroll
        for (int r = 0; r < 8; r++) cf[r] = rstat[m0 + r];
#pragma unroll
        for (int r = 0; r < 8; r++)
#pragma unroll
            for (int c = 0; c < 8; c++) oacc[r][c] *= cf[r];

#pragma unroll 4
        for (int n = 0; n < 64; n++) {
            float4 vlo = *(const float4*)&Vs[n*260 + lane*4];
            float4 vhi = *(const float4*)&Vs[n*260 + 128 + lane*4];
#pragma unroll
            for (int r = 0; r < 8; r++) {
                float p = Ps[(m0+r)*68 + n];
                oacc[r][0] += p*vlo.x; oacc[r][1] += p*vlo.y;
                oacc[r][2] += p*vlo.z; oacc[r][3] += p*vlo.w;
                oacc[r][4] += p*vhi.x; oacc[r][5] += p*vhi.y;
                oacc[r][6] += p*vhi.z; oacc[r][7] += p*vhi.w;
            }
        }
    }

    __syncthreads();
    if (tx == 0) {
#pragma unroll
        for (int i = 0; i < 4; i++) rstat[ty*4 + i] = 1.f / lrun[i];
    }
    __syncthreads();

    float* og = O + (size_t)qrow0*HH + h*256;
#pragma unroll
    for (int r = 0; r < 8; r++) {
        float linv = rstat[m0 + r];
        *(float4*)&og[(size_t)(m0+r)*HH + lane*4] =
            make_float4(oacc[r][0]*linv, oacc[r][1]*linv,
                        oacc[r][2]*linv, oacc[r][3]*linv);
        *(float4*)&og[(size_t)(m0+r)*HH + 128 + lane*4] =
            make_float4(oacc[r][4]*linv, oacc[r][5]*linv,
                        oacc[r][6]*linv, oacc[r][7]*linv);
    }
}

// ------------------------ host launch -----------------------------------------
extern "C" void kernel_launch(void* const* d_in, const int* in_sizes, int n_in,
                              void* d_out, int out_size) {
    const float* X        = (const float*)d_in[0];
    const int*   msk      = (const int*)  d_in[1];
    const float* cv       = (const float*)d_in[2];
    const float* Wq       = (const float*)d_in[3];
    const float* bq       = (const float*)d_in[4];
    const float* Wk       = (const float*)d_in[5];
    const float* bk       = (const float*)d_in[6];
    const float* Wv       = (const float*)d_in[7];
    const float* bv       = (const float*)d_in[8];
    const float* Wg       = (const float*)d_in[9];
    const float* bg       = (const float*)d_in[10];
    const float* Wa       = (const float*)d_in[11];
    const float* ba       = (const float*)d_in[12];
    const float* ca_in_w  = (const float*)d_in[13];
    const float* ca_in_b  = (const float*)d_in[14];
    const float* ca_out_w = (const float*)d_in[15];
    const float* ca_out_b = (const float*)d_in[16];
    const float* ma_in_w  = (const float*)d_in[17];
    const float* ma_in_b  = (const float*)d_in[18];
    const float* ma_out_w = (const float*)d_in[19];
    const float* ma_out_b = (const float*)d_in[20];
    const float* Wo       = (const float*)d_in[21];
    const float* bo       = (const float*)d_in[22];
    float* out = (float*)d_out;

    float *q, *k, *v, *ctx, *bctx, *qkv, *modv, *aw;
    cudaGetSymbolAddress((void**)&q,    g_q);
    cudaGetSymbolAddress((void**)&k,    g_k);
    cudaGetSymbolAddress((void**)&v,    g_v);
    cudaGetSymbolAddress((void**)&ctx,  g_ctx);
    cudaGetSymbolAddress((void**)&bctx, g_bctx);
    cudaGetSymbolAddress((void**)&qkv,  g_qkv);
    cudaGetSymbolAddress((void**)&modv, g_mod);
    cudaGetSymbolAddress((void**)&aw,   g_aw);

    const int smem_main = 4*64*68*(int)sizeof(float);                     // ~69.6 KB
    const int smem_br   = (256*68 + 64*68 + 64*260 + 64*68 + 64)
                          * (int)sizeof(float);                           // ~171.3 KB
    cudaFuncSetAttribute(flash_main,
                         cudaFuncAttributeMaxDynamicSharedMemorySize, smem_main);
    cudaFuncSetAttribute(flash_branch,
                         cudaFuncAttributeMaxDynamicSharedMemorySize, smem_br);

    dim3 gN(HH/128, NROWS/128);   // (8, 32)
    dim3 g3(H3/128, NROWS/128);   // (24, 32)

    awareness_kernel<<<1, 32>>>(cv, Wa, ba, aw);
    modulation_kernel<<<(NROWS*NH)/256, 256>>>(X, Wg, bg, aw, modv);

    sgemm<<<gN, 256>>>(X, Wq, bq, nullptr, q, NROWS, HH, HH, 1.f, 0.f);
    sgemm<<<gN, 256>>>(X, Wk, bk, nullptr, k, NROWS, HH, HH, 1.f, 0.f);
    sgemm<<<gN, 256>>>(X, Wv, bv, nullptr, v, NROWS, HH, HH, 1.f, 0.f);

    flash_main<<<dim3(SS/64, NH, BB), 256, smem_main>>>(q, k, v, modv, msk, ctx);

    // causal branch: ctx = 0.3*ctx + 0.7*(branch_attn(X) @ ca_out_w + b)
    sgemm<<<g3, 256>>>(X, ca_in_w, ca_in_b, nullptr, qkv, NROWS, H3, HH, 1.f, 0.f);
    flash_branch<<<dim3(SS/64, 4, BB), 256, smem_br>>>(qkv, bctx, 0.0625f);
    sgemm<<<gN, 256>>>(bctx, ca_out_w, ca_out_b, ctx, ctx, NROWS, HH, HH, 0.7f, 0.3f);

    // metacognitive branch: ctx = 0.85*ctx + 0.15*(branch_attn(ctx) @ ma_out_w + b)
    sgemm<<<g3, 256>>>(ctx, ma_in_w, ma_in_b, nullptr, qkv, NROWS, H3, HH, 1.f, 0.f);
    flash_branch<<<dim3(SS/64, 4, BB), 256, smem_br>>>(qkv, bctx, 0.0625f);
    sgemm<<<gN, 256>>>(bctx, ma_out_w, ma_out_b, ctx, ctx, NROWS, HH, HH, 0.15f, 0.85f);

    // final projection
    sgemm<<<gN, 256>>>(ctx, Wo, bo, nullptr, out, NROWS, HH, HH, 1.f, 0.f);
}

// round 4
// speedup vs baseline: 1.4028x; 1.4028x over previous
#include <cuda_runtime.h>
#include <cstdint>

#define BB 2
#define SS 2048
#define HH 1024
#define NH 16
#define H3 3072
#define NROWS (BB*SS)   // 4096

// Does this compilation pass have arch-specific sm_100a/sm_103a features?
#if defined(__CUDA_ARCH_FEAT_SM103_ALL) || defined(__CUDA_ARCH_FEAT_SM100_ALL) || \
    (defined(__CUDA_ARCH_SPECIFIC__) && (__CUDA_ARCH_SPECIFIC__ >= 1000)) || \
    (defined(__CUDA_ARCH_FAMILY_SPECIFIC__) && (__CUDA_ARCH_FAMILY_SPECIFIC__ >= 1000))
#define HAS_TCGEN05 1
#else
#define HAS_TCGEN05 0
#endif

// ------------------------ scratch (__device__ globals; no allocation) ---------
__device__ float g_q[NROWS*HH];
__device__ float g_k[NROWS*HH];
__device__ float g_v[NROWS*HH];
__device__ float g_ctx[NROWS*HH];
__device__ float g_bctx[NROWS*HH];
__device__ float g_qkv[NROWS*H3];
__device__ float g_mod[NROWS*NH];
__device__ float g_aw[NH];
// pre-transposed weights [N][K]
__device__ float g_wtq[HH*HH];
__device__ float g_wtk[HH*HH];
__device__ float g_wtv[HH*HH];
__device__ float g_wtci[H3*HH];
__device__ float g_wtco[HH*HH];
__device__ float g_wtmi[H3*HH];
__device__ float g_wtmo[HH*HH];
__device__ float g_wto[HH*HH];

// ======================= PTX helpers (guarded, sm_103a only) ==================
#if HAS_TCGEN05 || !defined(__CUDA_ARCH__)
// (definitions are harmless in host pass; only instantiated when called)
#endif

static __device__ __forceinline__ uint32_t smem_u32(const void* p) {
    uint32_t a;
    asm("{ .reg .u64 t; cvta.to.shared.u64 t, %1; cvt.u32.u64 %0, t; }"
        : "=r"(a) : "l"(p));
    return a;
}

static __device__ __forceinline__ uint32_t elect_one_pred() {
    uint32_t pred;
    asm volatile(
        "{\n\t"
        ".reg .pred p;\n\t"
        "elect.sync _|p, 0xFFFFFFFF;\n\t"
        "selp.b32 %0, 1, 0, p;\n\t"
        "}" : "=r"(pred));
    return pred;
}

#define MBARRIER_INIT(addr, count) \
    asm volatile("mbarrier.init.shared.b64 [%0], %1;" \
                 :: "r"((uint32_t)(addr)), "r"((uint32_t)(count)) : "memory")

#define MBARRIER_WAIT_PARITY(mbar_smem_addr, phase_parity) do { \
    uint32_t _mbar = (uint32_t)(mbar_smem_addr); \
    uint32_t _parity = (uint32_t)(phase_parity); \
    uint32_t _done; \
    asm volatile( \
        "{\n\t" \
        ".reg .pred p;\n\t" \
        "mbarrier.try_wait.parity.acquire.cta.shared::cta.b64 p, [%1], %2;\n\t" \
        "selp.b32 %0, 1, 0, p;\n\t" \
        "}" \
        : "=r"(_done) : "r"(_mbar), "r"(_parity) : "memory"); \
    if (!_done) { \
        asm volatile( \
            "{\n\t" \
            ".reg .pred P1;\n\t" \
            "WAIT_LOOP_%=:\n\t" \
            "mbarrier.try_wait.parity.acquire.cta.shared::cta.b64 P1, [%0], %1, 0x989680;\n\t" \
            "@P1 bra.uni WAIT_DONE_%=;\n\t" \
            "bra.uni WAIT_LOOP_%=;\n\t" \
            "WAIT_DONE_%=:\n\t" \
            "}" \
            :: "r"(_mbar), "r"(_parity) : "memory"); \
    } \
} while(0)

#if HAS_TCGEN05

#define TCGEN05_ALLOC(smem_result_addr, nCols) \
    asm volatile("tcgen05.alloc.cta_group::1.sync.aligned.shared::cta.b32 [%0], %1;" \
                 :: "r"((uint32_t)(smem_result_addr)), "r"((uint32_t)(nCols)) : "memory")
#define TCGEN05_DEALLOC(tmem_addr, nCols) \
    asm volatile("tcgen05.dealloc.cta_group::1.sync.aligned.b32 %0, %1;" \
                 :: "r"(tmem_addr), "r"((uint32_t)(nCols)))
#define TCGEN05_RELINQUISH() \
    asm volatile("tcgen05.relinquish_alloc_permit.cta_group::1.sync.aligned;")
#define TCGEN05_COMMIT(mbar_smem_addr) \
    asm volatile("tcgen05.commit.cta_group::1.mbarrier::arrive::one.shared::cluster.b64 [%0];" \
                 :: "r"((uint32_t)(mbar_smem_addr)) : "memory")
#define TCGEN05_FENCE_AFTER() \
    asm volatile("tcgen05.fence::after_thread_sync;" ::: "memory")
#define TCGEN05_FENCE_BEFORE() \
    asm volatile("tcgen05.fence::before_thread_sync;" ::: "memory")
#define TCGEN05_WAIT_LD() \
    asm volatile("tcgen05.wait::ld.sync.aligned;" ::: "memory")

#define TCGEN05_LD_32X32B_X32(r, tmem_addr) \
    asm volatile( \
        "tcgen05.ld.sync.aligned.32x32b.x32.b32 " \
        "{%0, %1, %2, %3, %4, %5, %6, %7, " \
        " %8, %9, %10, %11, %12, %13, %14, %15, " \
        " %16, %17, %18, %19, %20, %21, %22, %23, " \
        " %24, %25, %26, %27, %28, %29, %30, %31}, [%32];" \
        : "=r"((r)[0]),  "=r"((r)[1]),  "=r"((r)[2]),  "=r"((r)[3]), \
          "=r"((r)[4]),  "=r"((r)[5]),  "=r"((r)[6]),  "=r"((r)[7]), \
          "=r"((r)[8]),  "=r"((r)[9]),  "=r"((r)[10]), "=r"((r)[11]), \
          "=r"((r)[12]), "=r"((r)[13]), "=r"((r)[14]), "=r"((r)[15]), \
          "=r"((r)[16]), "=r"((r)[17]), "=r"((r)[18]), "=r"((r)[19]), \
          "=r"((r)[20]), "=r"((r)[21]), "=r"((r)[22]), "=r"((r)[23]), \
          "=r"((r)[24]), "=r"((r)[25]), "=r"((r)[26]), "=r"((r)[27]), \
          "=r"((r)[28]), "=r"((r)[29]), "=r"((r)[30]), "=r"((r)[31]) \
        : "r"(tmem_addr))

static __device__ __forceinline__ void mma_tf32_ss(
    uint32_t d_tmem, uint64_t a_desc, uint64_t b_desc, uint32_t idesc, bool acc) {
    uint32_t en = acc ? 1u : 0u;
    asm volatile(
        "{\n\t"
        ".reg .pred p;\n\t"
        "setp.ne.u32 p, %4, 0;\n\t"
        "tcgen05.mma.cta_group::1.kind::tf32 [%0], %1, %2, %3, p;\n\t"
        "}"
        :: "r"(d_tmem), "l"(a_desc), "l"(b_desc), "r"(idesc), "r"(en)
        : "memory");
}

#endif  // HAS_TCGEN05

static constexpr uint64_t SMEM_DESC_BASE_SW128 =
    (uint64_t(2)  << 61) | (uint64_t(1) << 46) | (uint64_t(64) << 32) | (uint64_t(1) << 16);
#define MAKE_SMEM_DESC(base_addr) \
    (SMEM_DESC_BASE_SW128 | ((uint64_t)((base_addr) >> 4) & 0x3FFF))

static __device__ __forceinline__ void split_tf32(float x, uint32_t& hi, uint32_t& lo) {
    asm("cvt.rna.tf32.f32 %0, %1;" : "=r"(hi) : "f"(x));
    float h = __uint_as_float(hi);
    float l = x - h;
    asm("cvt.rna.tf32.f32 %0, %1;" : "=r"(lo) : "f"(l));
}

static __device__ __forceinline__ void split4(float4 v, uint4& hi, uint4& lo) {
    split_tf32(v.x, hi.x, lo.x);
    split_tf32(v.y, hi.y, lo.y);
    split_tf32(v.z, hi.z, lo.z);
    split_tf32(v.w, hi.w, lo.w);
}

// ------------------------ weight transpose: Wt[n][k] = W[k][n] ----------------
__global__ __launch_bounds__(256) void transpose_w(
    const float* __restrict__ W, float* __restrict__ Wt, int K, int N) {
    __shared__ float t[32][33];
    int n0 = blockIdx.x*32, k0 = blockIdx.y*32;
    int x = threadIdx.x, y = threadIdx.y;
#pragma unroll
    for (int i = 0; i < 32; i += 8)
        t[y+i][x] = W[(size_t)(k0+y+i)*N + n0+x];
    __syncthreads();
#pragma unroll
    for (int i = 0; i < 32; i += 8)
        Wt[(size_t)(n0+y+i)*K + k0+x] = t[x][y+i];
}

// ------------------------ awareness ------------------------------------------
__global__ void awareness_kernel(const float* __restrict__ cv,
                                 const float* __restrict__ Wa,
                                 const float* __restrict__ ba,
                                 float* __restrict__ aw) {
    int h = threadIdx.x;
    if (h < NH) {
        float s = ba[h];
#pragma unroll
        for (int c = 0; c < 16; c++) s += cv[c] * Wa[c*NH + h];
        aw[h] = s;
    }
}

// ------------------------ modulation: block per row ---------------------------
__global__ __launch_bounds__(128) void modulation2(
    const float* __restrict__ X, const float* __restrict__ Wg,
    const float* __restrict__ bg, const float* __restrict__ aw,
    float* __restrict__ modv) {
    __shared__ float red[4][16];
    int row = blockIdx.x, t = threadIdx.x;
    int lane = t & 31, w = t >> 5;
    const float* x = X + (size_t)row * HH;
    float4 x0 = *(const float4*)(x + t*8);
    float4 x1 = *(const float4*)(x + t*8 + 4);
    float xv[8] = {x0.x,x0.y,x0.z,x0.w,x1.x,x1.y,x1.z,x1.w};
    float acc[16];
#pragma unroll
    for (int h = 0; h < 16; h++) acc[h] = 0.f;
#pragma unroll
    for (int kk = 0; kk < 8; kk++) {
        const float4* wr = (const float4*)(Wg + (size_t)(t*8 + kk)*16);
        float4 w0 = wr[0], w1 = wr[1], w2 = wr[2], w3 = wr[3];
        float v = xv[kk];
        acc[0]+=v*w0.x; acc[1]+=v*w0.y; acc[2]+=v*w0.z; acc[3]+=v*w0.w;
        acc[4]+=v*w1.x; acc[5]+=v*w1.y; acc[6]+=v*w1.z; acc[7]+=v*w1.w;
        acc[8]+=v*w2.x; acc[9]+=v*w2.y; acc[10]+=v*w2.z; acc[11]+=v*w2.w;
        acc[12]+=v*w3.x; acc[13]+=v*w3.y; acc[14]+=v*w3.z; acc[15]+=v*w3.w;
    }
#pragma unroll
    for (int h = 0; h < 16; h++) {
#pragma unroll
        for (int o = 16; o >= 1; o >>= 1)
            acc[h] += __shfl_xor_sync(0xffffffffu, acc[h], o);
    }
    if (lane == 0) {
#pragma unroll
        for (int h = 0; h < 16; h++) red[w][h] = acc[h];
    }
    __syncthreads();
    if (t < 16) {
        float s = red[0][t] + red[1][t] + red[2][t] + red[3][t] + bg[t] + aw[t];
        modv[(size_t)row*16 + t] = 1.f / (1.f + __expf(-s));
    }
}

// ======================= tcgen05 tf32 GEMM ====================================
// C[M,N] = alpha*(A[M,K] @ Bt[N,K]^T + bias[N]) + beta*Cold
// 3xTF32 split for fp32 accuracy. Tile 128m x 256n, K-step 32, double-buffered.
#define GTN 256
#define GBUF 98304   // per-buffer smem bytes: Ah 16K, Al 16K, Bh 32K, Bl 32K
#define GSMEM (2048 + 1024 + 2*GBUF)

__global__ __launch_bounds__(128, 1)
void tf32_gemm(const float* __restrict__ A, const float* __restrict__ Bt,
               const float* __restrict__ bias, const float* __restrict__ Cold,
               float* __restrict__ C, int M, int N, int K, float alpha, float beta)
{
#if HAS_TCGEN05
    extern __shared__ char smraw[];
    uint32_t smb = smem_u32(smraw);
    uint32_t ctrl = smb;
    uint32_t tiles_u = (smb + 2048 + 1023) & ~1023u;
    char* tiles_p = smraw + (tiles_u - smb);
    float* sbias = (float*)(smraw + 64);
    const int tid = threadIdx.x;
    const int lane = tid & 31, wid = tid >> 5;
    const int nbase = blockIdx.x * GTN, mbase = blockIdx.y * 128;

    if (tid == 0) { MBARRIER_INIT(ctrl + 0, 1); MBARRIER_INIT(ctrl + 8, 1); }
    if (wid == 0) {
        TCGEN05_ALLOC(ctrl + 16, 256);
        TCGEN05_RELINQUISH();
    }
    sbias[tid]       = bias[nbase + tid];
    sbias[tid + 128] = bias[nbase + tid + 128];
    __syncthreads();
    uint32_t tmem;
    asm volatile("ld.shared.b32 %0, [%1];" : "=r"(tmem) : "r"(ctrl + 16));

    const float* arow  = A  + (size_t)(mbase + tid) * K;
    const float* brow0 = Bt + (size_t)(nbase + tid) * K;
    const float* brow1 = Bt + (size_t)(nbase + tid + 128) * K;
    const uint32_t xr = (uint32_t)(tid & 7) << 4;   // SW128 xor (same for tid+128)
    const uint32_t arb = (uint32_t)tid * 128;
    const uint32_t brb0 = (uint32_t)tid * 128;
    const uint32_t brb1 = (uint32_t)(tid + 128) * 128;

    int ph0 = 0, ph1 = 0;
    const uint32_t idesc = (1u<<4) | (2u<<7) | (2u<<10) | ((GTN/8)<<17) | (8u<<24);
    const int nsteps = K / 32;
    for (int s = 0; s < nsteps; s++) {
        int buf = s & 1;
        if (s >= 2) {
            if (buf == 0) { MBARRIER_WAIT_PARITY(ctrl + 0, ph0); ph0 ^= 1; }
            else          { MBARRIER_WAIT_PARITY(ctrl + 8, ph1); ph1 ^= 1; }
        }
        char* tb = tiles_p + buf * GBUF;
        const float4* ap  = (const float4*)(arow  + s*32);
        const float4* bp0 = (const float4*)(brow0 + s*32);
        const float4* bp1 = (const float4*)(brow1 + s*32);
#pragma unroll
        for (int c = 0; c < 8; c++) {
            uint32_t sw = ((uint32_t)(c * 16)) ^ xr;
            uint4 hi, lo;
            float4 v = ap[c];
            split4(v, hi, lo);
            *(uint4*)(tb + arb + sw)          = hi;
            *(uint4*)(tb + 16384 + arb + sw)  = lo;
            v = bp0[c];
            split4(v, hi, lo);
            *(uint4*)(tb + 32768 + brb0 + sw) = hi;
            *(uint4*)(tb + 65536 + brb0 + sw) = lo;
            v = bp1[c];
            split4(v, hi, lo);
            *(uint4*)(tb + 32768 + brb1 + sw) = hi;
            *(uint4*)(tb + 65536 + brb1 + sw) = lo;
        }
        asm volatile("fence.proxy.async.shared::cta;" ::: "memory");
        __syncthreads();
        if (wid == 0) {
            if (elect_one_pred()) {
                uint32_t base = tiles_u + buf * GBUF;
                uint64_t dAh = MAKE_SMEM_DESC(base);
                uint64_t dAl = MAKE_SMEM_DESC(base + 16384);
                uint64_t dBh = MAKE_SMEM_DESC(base + 32768);
                uint64_t dBl = MAKE_SMEM_DESC(base + 65536);
#pragma unroll
                for (int sub = 0; sub < 4; sub++)
                    mma_tf32_ss(tmem, dAh + sub*2, dBh + sub*2, idesc, !(s == 0 && sub == 0));
#pragma unroll
                for (int sub = 0; sub < 4; sub++)
                    mma_tf32_ss(tmem, dAh + sub*2, dBl + sub*2, idesc, true);
#pragma unroll
                for (int sub = 0; sub < 4; sub++)
                    mma_tf32_ss(tmem, dAl + sub*2, dBh + sub*2, idesc, true);
                TCGEN05_COMMIT(ctrl + buf * 8);
            }
        }
    }
    MBARRIER_WAIT_PARITY(ctrl + 0, ph0);
    MBARRIER_WAIT_PARITY(ctrl + 8, ph1);
    TCGEN05_FENCE_AFTER();

    const int row = mbase + wid*32 + lane;
#pragma unroll 1
    for (int cc = 0; cc < 8; cc++) {
        uint32_t d[32];
        TCGEN05_LD_32X32B_X32(d, tmem + cc*32);
        TCGEN05_WAIT_LD();
        const int col = nbase + cc*32;
        float* cp = C + (size_t)row * N + col;
        const float* oldp = Cold + (size_t)row * N + col;
#pragma unroll
        for (int j = 0; j < 32; j += 4) {
            float4 o;
            o.x = alpha * (__uint_as_float(d[j+0]) + sbias[cc*32 + j + 0]);
            o.y = alpha * (__uint_as_float(d[j+1]) + sbias[cc*32 + j + 1]);
            o.z = alpha * (__uint_as_float(d[j+2]) + sbias[cc*32 + j + 2]);
            o.w = alpha * (__uint_as_float(d[j+3]) + sbias[cc*32 + j + 3]);
            if (beta != 0.f) {
                float4 ov = *(const float4*)(oldp + j);
                o.x += beta*ov.x; o.y += beta*ov.y; o.z += beta*ov.z; o.w += beta*ov.w;
            }
            *(float4*)(cp + j) = o;
        }
    }
    TCGEN05_FENCE_BEFORE();
    __syncthreads();
    if (tid == 0) {
        asm volatile("mbarrier.inval.shared.b64 [%0];" :: "r"(ctrl + 0) : "memory");
        asm volatile("mbarrier.inval.shared.b64 [%0];" :: "r"(ctrl + 8) : "memory");
    }
    __syncthreads();
    if (wid == 0) TCGEN05_DEALLOC(tmem, 256);
#else
    // SIMT fallback for non-arch-specific compilation passes (never expected to
    // run on GB300; present only so every gencode target links a correct body).
    const int tid = threadIdx.x;
    const int nbase = blockIdx.x * GTN, mbase = blockIdx.y * 128;
    const int row = mbase + tid;
    const float* arow = A + (size_t)row * K;
    for (int n = 0; n < GTN; n++) {
        const float* brow = Bt + (size_t)(nbase + n) * K;
        float s = 0.f;
        for (int k = 0; k < K; k++) s += arow[k] * brow[k];
        float o = alpha * (s + bias[nbase + n]);
        if (beta != 0.f) o += beta * Cold[(size_t)row * N + nbase + n];
        C[(size_t)row * N + nbase + n] = o;
    }
#endif
}

// ------------------------ flash attention, main (16 heads, hd=64) -------------
__global__ __launch_bounds__(256) void flash_main(
    const float* __restrict__ Q, const float* __restrict__ K,
    const float* __restrict__ V, const float* __restrict__ modv,
    const int* __restrict__ mask, float* __restrict__ O)
{
    extern __shared__ float sm[];
    float* Qs = sm;
    float* Ks = sm + 64*68;
    float* Vs = sm + 2*64*68;
    float* Ps = sm + 3*64*68;
    const int tid = threadIdx.x;
    const int tx = tid & 15, ty = tid >> 4;
    const int qt = blockIdx.x, h = blockIdx.y, b = blockIdx.z;
    const int qrow0 = b*SS + qt*64;

    const float* qg = Q + (size_t)qrow0 * HH + h*64;
#pragma unroll
    for (int i = 0; i < 16; i++) {
        int idx = tid + i*256;
        int m = idx >> 6, d = idx & 63;
        Qs[d*68 + m] = qg[(size_t)m*HH + d];
    }

    float mrow[4];
#pragma unroll
    for (int i = 0; i < 4; i++)
        mrow[i] = modv[(size_t)(qrow0 + ty*4 + i)*NH + h] * 0.125f;

    float oacc[4][4];
#pragma unroll
    for (int i = 0; i < 4; i++)
#pragma unroll
        for (int j = 0; j < 4; j++) oacc[i][j] = 0.f;
    float mrun[4], lrun[4];
#pragma unroll
    for (int i = 0; i < 4; i++) { mrun[i] = -1e30f; lrun[i] = 0.f; }

    for (int kt = 0; kt < SS/64; kt++) {
        const int krow0 = b*SS + kt*64;
        const float* kg = K + (size_t)krow0*HH + h*64;
        const float* vg = V + (size_t)krow0*HH + h*64;
        __syncthreads();
#pragma unroll
        for (int i = 0; i < 16; i++) {
            int idx = tid + i*256;
            int n = idx >> 6, d = idx & 63;
            Ks[d*68 + n] = kg[(size_t)n*HH + d];
            Vs[n*68 + d] = vg[(size_t)n*HH + d];
        }
        __syncthreads();

        float sacc[4][4];
#pragma unroll
        for (int i = 0; i < 4; i++)
#pragma unroll
            for (int j = 0; j < 4; j++) sacc[i][j] = 0.f;
#pragma unroll 8
        for (int d = 0; d < 64; d++) {
            float4 qv = *(const float4*)&Qs[d*68 + ty*4];
            float4 kv = *(const float4*)&Ks[d*68 + tx*4];
            float qa[4] = {qv.x,qv.y,qv.z,qv.w};
            float ka[4] = {kv.x,kv.y,kv.z,kv.w};
#pragma unroll
            for (int i = 0; i < 4; i++)
#pragma unroll
                for (int j = 0; j < 4; j++)
                    sacc[i][j] += qa[i]*ka[j];
        }

        float mk[4];
#pragma unroll
        for (int j = 0; j < 4; j++)
            mk[j] = mask[krow0 + tx*4 + j] ? 0.f : -1e30f;

#pragma unroll
        for (int i = 0; i < 4; i++) {
            float srow[4], rmax = -1e30f;
#pragma unroll
            for (int j = 0; j < 4; j++) {
                srow[j] = sacc[i][j]*mrow[i] + mk[j];
                rmax = fmaxf(rmax, srow[j]);
            }
#pragma unroll
            for (int off = 1; off < 16; off <<= 1)
                rmax = fmaxf(rmax, __shfl_xor_sync(0xffffffffu, rmax, off));
            float mnew = fmaxf(mrun[i], rmax);
            float corr = __expf(mrun[i] - mnew);
            float p[4]; float ls = 0.f;
#pragma unroll
            for (int j = 0; j < 4; j++) { p[j] = __expf(srow[j] - mnew); ls += p[j]; }
#pragma unroll
            for (int off = 1; off < 16; off <<= 1)
                ls += __shfl_xor_sync(0xffffffffu, ls, off);
            lrun[i] = lrun[i]*corr + ls;
            mrun[i] = mnew;
#pragma unroll
            for (int j = 0; j < 4; j++) oacc[i][j] *= corr;
            *(float4*)&Ps[(ty*4+i)*68 + tx*4] = make_float4(p[0],p[1],p[2],p[3]);
        }
        __syncthreads();

#pragma unroll 8
        for (int n = 0; n < 64; n++) {
            float4 vv = *(const float4*)&Vs[n*68 + tx*4];
#pragma unroll
            for (int i = 0; i < 4; i++) {
                float p = Ps[(ty*4+i)*68 + n];
                oacc[i][0] += p*vv.x; oacc[i][1] += p*vv.y;
                oacc[i][2] += p*vv.z; oacc[i][3] += p*vv.w;
            }
        }
    }

    float* og = O + (size_t)qrow0*HH + h*64;
#pragma unroll
    for (int i = 0; i < 4; i++) {
        float linv = 1.f / lrun[i];
        *(float4*)&og[(size_t)(ty*4+i)*HH + tx*4] =
            make_float4(oacc[i][0]*linv, oacc[i][1]*linv,
                        oacc[i][2]*linv, oacc[i][3]*linv);
    }
}

// ------------------------ flash attention, branch MHA (4 heads, hd=256) -------
__global__ __launch_bounds__(256, 1) void flash_branch(
    const float* __restrict__ QKV, float* __restrict__ O, float scale)
{
    extern __shared__ float sm[];
    float* Qs   = sm;
    float* Ks   = Qs + 256*68;
    float* Vs   = Ks + 64*68;
    float* Ps   = Vs + 64*260;
    float* rstat= Ps + 64*68;
    const int tid = threadIdx.x;
    const int tx = tid & 15, ty = tid >> 4;
    const int lane = tid & 31, wrp = tid >> 5;
    const int m0 = wrp * 8;
    const int qt = blockIdx.x, h = blockIdx.y, b = blockIdx.z;
    const int qrow0 = b*SS + qt*64;

    const float* qg = QKV + (size_t)qrow0*H3 + h*256;
#pragma unroll 4
    for (int i = 0; i < 64; i++) {
        int idx = tid + i*256;
        int m = idx >> 8, d = idx & 255;
        Qs[d*68 + m] = qg[(size_t)m*H3 + d];
    }

    float oacc[8][8];
#pragma unroll
    for (int r = 0; r < 8; r++)
#pragma unroll
        for (int c = 0; c < 8; c++) oacc[r][c] = 0.f;
    float mrun[4], lrun[4];
#pragma unroll
    for (int i = 0; i < 4; i++) { mrun[i] = -1e30f; lrun[i] = 0.f; }

    for (int kt = 0; kt < SS/64; kt++) {
        const int krow0 = b*SS + kt*64;
        const float* kg = QKV + (size_t)krow0*H3 + HH   + h*256;
        const float* vg = QKV + (size_t)krow0*H3 + 2*HH + h*256;
        __syncthreads();
#pragma unroll 4
        for (int i = 0; i < 64; i++) {
            int idx = tid + i*256;
            int n = idx >> 8, d = idx & 255;
            Vs[n*260 + d] = vg[(size_t)n*H3 + d];
        }

        float sacc[4][4];
#pragma unroll
        for (int i = 0; i < 4; i++)
#pragma unroll
            for (int j = 0; j < 4; j++) sacc[i][j] = 0.f;

        for (int dc = 0; dc < 4; dc++) {
            __syncthreads();
#pragma unroll
            for (int i = 0; i < 16; i++) {
                int idx = tid + i*256;
                int n = idx >> 6, d = idx & 63;
                Ks[d*68 + n] = kg[(size_t)n*H3 + dc*64 + d];
            }
            __syncthreads();
#pragma unroll 8
            for (int d = 0; d < 64; d++) {
                float4 qv = *(const float4*)&Qs[(dc*64 + d)*68 + ty*4];
                float4 kv = *(const float4*)&Ks[d*68 + tx*4];
                float qa[4] = {qv.x,qv.y,qv.z,qv.w};
                float ka[4] = {kv.x,kv.y,kv.z,kv.w};
#pragma unroll
                for (int i = 0; i < 4; i++)
#pragma unroll
                    for (int j = 0; j < 4; j++)
                        sacc[i][j] += qa[i]*ka[j];
            }
        }

#pragma unroll
        for (int i = 0; i < 4; i++) {
            float srow[4], rmax = -1e30f;
#pragma unroll
            for (int j = 0; j < 4; j++) {
                srow[j] = sacc[i][j] * scale;
                rmax = fmaxf(rmax, srow[j]);
            }
#pragma unroll
            for (int off = 1; off < 16; off <<= 1)
                rmax = fmaxf(rmax, __shfl_xor_sync(0xffffffffu, rmax, off));
            float mnew = fmaxf(mrun[i], rmax);
            float corr = __expf(mrun[i] - mnew);
            float p[4]; float ls = 0.f;
#pragma unroll
            for (int j = 0; j < 4; j++) { p[j] = __expf(srow[j] - mnew); ls += p[j]; }
#pragma unroll
            for (int off = 1; off < 16; off <<= 1)
                ls += __shfl_xor_sync(0xffffffffu, ls, off);
            lrun[i] = lrun[i]*corr + ls;
            mrun[i] = mnew;
            if (tx == 0) rstat[ty*4 + i] = corr;
            *(float4*)&Ps[(ty*4+i)*68 + tx*4] = make_float4(p[0],p[1],p[2],p[3]);
        }
        __syncthreads();

        float cf[8];
#pragma unroll
        for (int r = 0; r < 8; r++) cf[r] = rstat[m0 + r];
#pragma unroll
        for (int r = 0; r < 8; r++)
#pragma unroll
            for (int c = 0; c < 8; c++) oacc[r][c] *= cf[r];

#pragma unroll 4
        for (int n = 0; n < 64; n++) {
            float4 vlo = *(const float4*)&Vs[n*260 + lane*4];
            float4 vhi = *(const float4*)&Vs[n*260 + 128 + lane*4];
#pragma unroll
            for (int r = 0; r < 8; r++) {
                float p = Ps[(m0+r)*68 + n];
                oacc[r][0] += p*vlo.x; oacc[r][1] += p*vlo.y;
                oacc[r][2] += p*vlo.z; oacc[r][3] += p*vlo.w;
                oacc[r][4] += p*vhi.x; oacc[r][5] += p*vhi.y;
                oacc[r][6] += p*vhi.z; oacc[r][7] += p*vhi.w;
            }
        }
    }

    __syncthreads();
    if (tx == 0) {
#pragma unroll
        for (int i = 0; i < 4; i++) rstat[ty*4 + i] = 1.f / lrun[i];
    }
    __syncthreads();

    float* og = O + (size_t)qrow0*HH + h*256;
#pragma unroll
    for (int r = 0; r < 8; r++) {
        float linv = rstat[m0 + r];
        *(float4*)&og[(size_t)(m0+r)*HH + lane*4] =
            make_float4(oacc[r][0]*linv, oacc[r][1]*linv,
                        oacc[r][2]*linv, oacc[r][3]*linv);
        *(float4*)&og[(size_t)(m0+r)*HH + 128 + lane*4] =
            make_float4(oacc[r][4]*linv, oacc[r][5]*linv,
                        oacc[r][6]*linv, oacc[r][7]*linv);
    }
}

// ------------------------ host launch -----------------------------------------
extern "C" void kernel_launch(void* const* d_in, const int* in_sizes, int n_in,
                              void* d_out, int out_size) {
    const float* X        = (const float*)d_in[0];
    const int*   msk      = (const int*)  d_in[1];
    const float* cv       = (const float*)d_in[2];
    const float* Wq       = (const float*)d_in[3];
    const float* bq       = (const float*)d_in[4];
    const float* Wk       = (const float*)d_in[5];
    const float* bk       = (const float*)d_in[6];
    const float* Wv       = (const float*)d_in[7];
    const float* bv       = (const float*)d_in[8];
    const float* Wg       = (const float*)d_in[9];
    const float* bg       = (const float*)d_in[10];
    const float* Wa       = (const float*)d_in[11];
    const float* ba       = (const float*)d_in[12];
    const float* ca_in_w  = (const float*)d_in[13];
    const float* ca_in_b  = (const float*)d_in[14];
    const float* ca_out_w = (const float*)d_in[15];
    const float* ca_out_b = (const float*)d_in[16];
    const float* ma_in_w  = (const float*)d_in[17];
    const float* ma_in_b  = (const float*)d_in[18];
    const float* ma_out_w = (const float*)d_in[19];
    const float* ma_out_b = (const float*)d_in[20];
    const float* Wo       = (const float*)d_in[21];
    const float* bo       = (const float*)d_in[22];
    float* out = (float*)d_out;

    float *q, *k, *v, *ctx, *bctx, *qkv, *modv, *aw;
    float *wtq, *wtk, *wtv, *wtci, *wtco, *wtmi, *wtmo, *wto;
    cudaGetSymbolAddress((void**)&q,    g_q);
    cudaGetSymbolAddress((void**)&k,    g_k);
    cudaGetSymbolAddress((void**)&v,    g_v);
    cudaGetSymbolAddress((void**)&ctx,  g_ctx);
    cudaGetSymbolAddress((void**)&bctx, g_bctx);
    cudaGetSymbolAddress((void**)&qkv,  g_qkv);
    cudaGetSymbolAddress((void**)&modv, g_mod);
    cudaGetSymbolAddress((void**)&aw,   g_aw);
    cudaGetSymbolAddress((void**)&wtq,  g_wtq);
    cudaGetSymbolAddress((void**)&wtk,  g_wtk);
    cudaGetSymbolAddress((void**)&wtv,  g_wtv);
    cudaGetSymbolAddress((void**)&wtci, g_wtci);
    cudaGetSymbolAddress((void**)&wtco, g_wtco);
    cudaGetSymbolAddress((void**)&wtmi, g_wtmi);
    cudaGetSymbolAddress((void**)&wtmo, g_wtmo);
    cudaGetSymbolAddress((void**)&wto,  g_wto);

    const int smem_main = 4*64*68*(int)sizeof(float);
    const int smem_br   = (256*68 + 64*68 + 64*260 + 64*68 + 64)*(int)sizeof(float);
    cudaFuncSetAttribute(flash_main,
                         cudaFuncAttributeMaxDynamicSharedMemorySize, smem_main);
    cudaFuncSetAttribute(flash_branch,
                         cudaFuncAttributeMaxDynamicSharedMemorySize, smem_br);
    cudaFuncSetAttribute(tf32_gemm,
                         cudaFuncAttributeMaxDynamicSharedMemorySize, GSMEM);

    dim3 tb(32, 8);
    transpose_w<<<dim3(HH/32, HH/32), tb>>>(Wq, wtq, HH, HH);
    transpose_w<<<dim3(HH/32, HH/32), tb>>>(Wk, wtk, HH, HH);
    transpose_w<<<dim3(HH/32, HH/32), tb>>>(Wv, wtv, HH, HH);
    transpose_w<<<dim3(H3/32, HH/32), tb>>>(ca_in_w, wtci, HH, H3);
    transpose_w<<<dim3(HH/32, HH/32), tb>>>(ca_out_w, wtco, HH, HH);
    transpose_w<<<dim3(H3/32, HH/32), tb>>>(ma_in_w, wtmi, HH, H3);
    transpose_w<<<dim3(HH/32, HH/32), tb>>>(ma_out_w, wtmo, HH, HH);
    transpose_w<<<dim3(HH/32, HH/32), tb>>>(Wo, wto, HH, HH);

    awareness_kernel<<<1, 32>>>(cv, Wa, ba, aw);
    modulation2<<<NROWS, 128>>>(X, Wg, bg, aw, modv);

    dim3 gN(HH/GTN, NROWS/128);   // (4, 32)
    dim3 g3(H3/GTN, NROWS/128);   // (12, 32)

    tf32_gemm<<<gN, 128, GSMEM>>>(X, wtq, bq, nullptr, q, NROWS, HH, HH, 1.f, 0.f);
    tf32_gemm<<<gN, 128, GSMEM>>>(X, wtk, bk, nullptr, k, NROWS, HH, HH, 1.f, 0.f);
    tf32_gemm<<<gN, 128, GSMEM>>>(X, wtv, bv, nullptr, v, NROWS, HH, HH, 1.f, 0.f);

    flash_main<<<dim3(SS/64, NH, BB), 256, smem_main>>>(q, k, v, modv, msk, ctx);

    tf32_gemm<<<g3, 128, GSMEM>>>(X, wtci, ca_in_b, nullptr, qkv, NROWS, H3, HH, 1.f, 0.f);
    flash_branch<<<dim3(SS/64, 4, BB), 256, smem_br>>>(qkv, bctx, 0.0625f);
    tf32_gemm<<<gN, 128, GSMEM>>>(bctx, wtco, ca_out_b, ctx, ctx, NROWS, HH, HH, 0.7f, 0.3f);

    tf32_gemm<<<g3, 128, GSMEM>>>(ctx, wtmi, ma_in_b, nullptr, qkv, NROWS, H3, HH, 1.f, 0.f);
    flash_branch<<<dim3(SS/64, 4, BB), 256, smem_br>>>(qkv, bctx, 0.0625f);
    tf32_gemm<<<gN, 128, GSMEM>>>(bctx, wtmo, ma_out_b, ctx, ctx, NROWS, HH, HH, 0.15f, 0.85f);

    tf32_gemm<<<gN, 128, GSMEM>>>(ctx, wto, bo, nullptr, out, NROWS, HH, HH, 1.f, 0.f);
}

// round 6
// speedup vs baseline: 3.1116x; 2.2181x over previous
#include <cuda_runtime.h>
#include <cstdint>

#define BB 2
#define SS 2048
#define HH 1024
#define NH 16
#define H3 3072
#define NROWS (BB*SS)   // 4096

// Does this compilation pass have arch-specific sm_100a/sm_103a features?
#if defined(__CUDA_ARCH_FEAT_SM103_ALL) || defined(__CUDA_ARCH_FEAT_SM100_ALL) || \
    (defined(__CUDA_ARCH_SPECIFIC__) && (__CUDA_ARCH_SPECIFIC__ >= 1000)) || \
    (defined(__CUDA_ARCH_FAMILY_SPECIFIC__) && (__CUDA_ARCH_FAMILY_SPECIFIC__ >= 1000))
#define HAS_TCGEN05 1
#else
#define HAS_TCGEN05 0
#endif

// ------------------------ scratch (__device__ globals; no allocation) ---------
__device__ float g_q[NROWS*HH];
__device__ float g_k[NROWS*HH];
__device__ float g_v[NROWS*HH];
__device__ float g_ctx[NROWS*HH];
__device__ float g_bctx[NROWS*HH];
__device__ float g_qkv[NROWS*H3];
__device__ float g_mod[NROWS*NH];
__device__ float g_aw[NH];
// pre-transposed weights [N][K]
__device__ float g_wtq[HH*HH];
__device__ float g_wtk[HH*HH];
__device__ float g_wtv[HH*HH];
__device__ float g_wtci[H3*HH];
__device__ float g_wtco[HH*HH];
__device__ float g_wtmi[H3*HH];
__device__ float g_wtmo[HH*HH];
__device__ float g_wto[HH*HH];

// ======================= PTX helpers ==========================================
static __device__ __forceinline__ uint32_t smem_u32(const void* p) {
    uint32_t a;
    asm("{ .reg .u64 t; cvta.to.shared.u64 t, %1; cvt.u32.u64 %0, t; }"
        : "=r"(a) : "l"(p));
    return a;
}

static __device__ __forceinline__ uint32_t elect_one_pred() {
    uint32_t pred;
    asm volatile(
        "{\n\t"
        ".reg .pred p;\n\t"
        "elect.sync _|p, 0xFFFFFFFF;\n\t"
        "selp.b32 %0, 1, 0, p;\n\t"
        "}" : "=r"(pred));
    return pred;
}

#define MBARRIER_INIT(addr, count) \
    asm volatile("mbarrier.init.shared.b64 [%0], %1;" \
                 :: "r"((uint32_t)(addr)), "r"((uint32_t)(count)) : "memory")

#define MBARRIER_WAIT_PARITY(mbar_smem_addr, phase_parity) do { \
    uint32_t _mbar = (uint32_t)(mbar_smem_addr); \
    uint32_t _parity = (uint32_t)(phase_parity); \
    uint32_t _done; \
    asm volatile( \
        "{\n\t" \
        ".reg .pred p;\n\t" \
        "mbarrier.try_wait.parity.acquire.cta.shared::cta.b64 p, [%1], %2;\n\t" \
        "selp.b32 %0, 1, 0, p;\n\t" \
        "}" \
        : "=r"(_done) : "r"(_mbar), "r"(_parity) : "memory"); \
    if (!_done) { \
        asm volatile( \
            "{\n\t" \
            ".reg .pred P1;\n\t" \
            "WAIT_LOOP_%=:\n\t" \
            "mbarrier.try_wait.parity.acquire.cta.shared::cta.b64 P1, [%0], %1, 0x989680;\n\t" \
            "@P1 bra.uni WAIT_DONE_%=;\n\t" \
            "bra.uni WAIT_LOOP_%=;\n\t" \
            "WAIT_DONE_%=:\n\t" \
            "}" \
            :: "r"(_mbar), "r"(_parity) : "memory"); \
    } \
} while(0)

#if HAS_TCGEN05

#define TCGEN05_ALLOC(smem_result_addr, nCols) \
    asm volatile("tcgen05.alloc.cta_group::1.sync.aligned.shared::cta.b32 [%0], %1;" \
                 :: "r"((uint32_t)(smem_result_addr)), "r"((uint32_t)(nCols)) : "memory")
#define TCGEN05_DEALLOC(tmem_addr, nCols) \
    asm volatile("tcgen05.dealloc.cta_group::1.sync.aligned.b32 %0, %1;" \
                 :: "r"(tmem_addr), "r"((uint32_t)(nCols)))
#define TCGEN05_RELINQUISH() \
    asm volatile("tcgen05.relinquish_alloc_permit.cta_group::1.sync.aligned;")
#define TCGEN05_COMMIT(mbar_smem_addr) \
    asm volatile("tcgen05.commit.cta_group::1.mbarrier::arrive::one.shared::cluster.b64 [%0];" \
                 :: "r"((uint32_t)(mbar_smem_addr)) : "memory")
#define TCGEN05_FENCE_AFTER() \
    asm volatile("tcgen05.fence::after_thread_sync;" ::: "memory")
#define TCGEN05_FENCE_BEFORE() \
    asm volatile("tcgen05.fence::before_thread_sync;" ::: "memory")
#define TCGEN05_WAIT_LD() \
    asm volatile("tcgen05.wait::ld.sync.aligned;" ::: "memory")
#define TCGEN05_WAIT_ST() \
    asm volatile("tcgen05.wait::st.sync.aligned;" ::: "memory")

#define TCGEN05_LD_32X32B_X32(r, tmem_addr) \
    asm volatile( \
        "tcgen05.ld.sync.aligned.32x32b.x32.b32 " \
        "{%0, %1, %2, %3, %4, %5, %6, %7, " \
        " %8, %9, %10, %11, %12, %13, %14, %15, " \
        " %16, %17, %18, %19, %20, %21, %22, %23, " \
        " %24, %25, %26, %27, %28, %29, %30, %31}, [%32];" \
        : "=r"((r)[0]),  "=r"((r)[1]),  "=r"((r)[2]),  "=r"((r)[3]), \
          "=r"((r)[4]),  "=r"((r)[5]),  "=r"((r)[6]),  "=r"((r)[7]), \
          "=r"((r)[8]),  "=r"((r)[9]),  "=r"((r)[10]), "=r"((r)[11]), \
          "=r"((r)[12]), "=r"((r)[13]), "=r"((r)[14]), "=r"((r)[15]), \
          "=r"((r)[16]), "=r"((r)[17]), "=r"((r)[18]), "=r"((r)[19]), \
          "=r"((r)[20]), "=r"((r)[21]), "=r"((r)[22]), "=r"((r)[23]), \
          "=r"((r)[24]), "=r"((r)[25]), "=r"((r)[26]), "=r"((r)[27]), \
          "=r"((r)[28]), "=r"((r)[29]), "=r"((r)[30]), "=r"((r)[31]) \
        : "r"(tmem_addr))

#define TCGEN05_ST_32X32B_X32(tmem_addr, r) \
    asm volatile( \
        "tcgen05.st.sync.aligned.32x32b.x32.b32 [%0], " \
        "{%1, %2, %3, %4, %5, %6, %7, %8, " \
        " %9, %10, %11, %12, %13, %14, %15, %16, " \
        " %17, %18, %19, %20, %21, %22, %23, %24, " \
        " %25, %26, %27, %28, %29, %30, %31, %32};" \
        :: "r"(tmem_addr), \
           "r"((r)[0]),  "r"((r)[1]),  "r"((r)[2]),  "r"((r)[3]), \
           "r"((r)[4]),  "r"((r)[5]),  "r"((r)[6]),  "r"((r)[7]), \
           "r"((r)[8]),  "r"((r)[9]),  "r"((r)[10]), "r"((r)[11]), \
           "r"((r)[12]), "r"((r)[13]), "r"((r)[14]), "r"((r)[15]), \
           "r"((r)[16]), "r"((r)[17]), "r"((r)[18]), "r"((r)[19]), \
           "r"((r)[20]), "r"((r)[21]), "r"((r)[22]), "r"((r)[23]), \
           "r"((r)[24]), "r"((r)[25]), "r"((r)[26]), "r"((r)[27]), \
           "r"((r)[28]), "r"((r)[29]), "r"((r)[30]), "r"((r)[31]) \
        : "memory")

static __device__ __forceinline__ void mma_tf32_ss(
    uint32_t d_tmem, uint64_t a_desc, uint64_t b_desc, uint32_t idesc, bool acc) {
    uint32_t en = acc ? 1u : 0u;
    asm volatile(
        "{\n\t"
        ".reg .pred p;\n\t"
        "setp.ne.u32 p, %4, 0;\n\t"
        "tcgen05.mma.cta_group::1.kind::tf32 [%0], %1, %2, %3, p;\n\t"
        "}"
        :: "r"(d_tmem), "l"(a_desc), "l"(b_desc), "r"(idesc), "r"(en)
        : "memory");
}

static __device__ __forceinline__ void mma_tf32_ts(
    uint32_t d_tmem, uint32_t a_tmem, uint64_t b_desc, uint32_t idesc, bool acc) {
    uint32_t en = acc ? 1u : 0u;
    asm volatile(
        "{\n\t"
        ".reg .pred p;\n\t"
        "setp.ne.u32 p, %4, 0;\n\t"
        "tcgen05.mma.cta_group::1.kind::tf32 [%0], [%1], %2, %3, p;\n\t"
        "}"
        :: "r"(d_tmem), "r"(a_tmem), "l"(b_desc), "r"(idesc), "r"(en)
        : "memory");
}

#endif  // HAS_TCGEN05

static constexpr uint64_t SMEM_DESC_BASE_SW128 =
    (uint64_t(2)  << 61) | (uint64_t(1) << 46) | (uint64_t(64) << 32) | (uint64_t(1) << 16);
#define MAKE_SMEM_DESC(base_addr) \
    (SMEM_DESC_BASE_SW128 | ((uint64_t)((base_addr) >> 4) & 0x3FFF))

#define SWZ128(off) ((off) ^ (((off) >> 3) & 0x70))

static __device__ __forceinline__ uint32_t f2tf32(float x) {
    uint32_t r;
    asm("cvt.rna.tf32.f32 %0, %1;" : "=r"(r) : "f"(x));
    return r;
}

static __device__ __forceinline__ void split_tf32(float x, uint32_t& hi, uint32_t& lo) {
    asm("cvt.rna.tf32.f32 %0, %1;" : "=r"(hi) : "f"(x));
    float h = __uint_as_float(hi);
    float l = x - h;
    asm("cvt.rna.tf32.f32 %0, %1;" : "=r"(lo) : "f"(l));
}

static __device__ __forceinline__ void split4(float4 v, uint4& hi, uint4& lo) {
    split_tf32(v.x, hi.x, lo.x);
    split_tf32(v.y, hi.y, lo.y);
    split_tf32(v.z, hi.z, lo.z);
    split_tf32(v.w, hi.w, lo.w);
}

// blocked K-major SW128 tf32 layout: [R rows x C cols], atom 8x32
static __device__ __forceinline__ uint32_t kmaj_off(int row, int k, int R) {
    uint32_t off = (uint32_t)((k >> 5) * (R * 128) + ((row >> 3) * 1024) +
                              ((row & 7) * 128) + ((k & 31) * 4));
    return SWZ128(off);
}

// ------------------------ weight transpose ------------------------------------
__global__ __launch_bounds__(256) void transpose_w(
    const float* __restrict__ W, float* __restrict__ Wt, int K, int N) {
    __shared__ float t[32][33];
    int n0 = blockIdx.x*32, k0 = blockIdx.y*32;
    int x = threadIdx.x, y = threadIdx.y;
#pragma unroll
    for (int i = 0; i < 32; i += 8)
        t[y+i][x] = W[(size_t)(k0+y+i)*N + n0+x];
    __syncthreads();
#pragma unroll
    for (int i = 0; i < 32; i += 8)
        Wt[(size_t)(n0+y+i)*K + k0+x] = t[x][y+i];
}

// ------------------------ awareness ------------------------------------------
__global__ void awareness_kernel(const float* __restrict__ cv,
                                 const float* __restrict__ Wa,
                                 const float* __restrict__ ba,
                                 float* __restrict__ aw) {
    int h = threadIdx.x;
    if (h < NH) {
        float s = ba[h];
#pragma unroll
        for (int c = 0; c < 16; c++) s += cv[c] * Wa[c*NH + h];
        aw[h] = s;
    }
}

// ------------------------ modulation ------------------------------------------
__global__ __launch_bounds__(128) void modulation2(
    const float* __restrict__ X, const float* __restrict__ Wg,
    const float* __restrict__ bg, const float* __restrict__ aw,
    float* __restrict__ modv) {
    __shared__ float red[4][16];
    int row = blockIdx.x, t = threadIdx.x;
    int lane = t & 31, w = t >> 5;
    const float* x = X + (size_t)row * HH;
    float4 x0 = *(const float4*)(x + t*8);
    float4 x1 = *(const float4*)(x + t*8 + 4);
    float xv[8] = {x0.x,x0.y,x0.z,x0.w,x1.x,x1.y,x1.z,x1.w};
    float acc[16];
#pragma unroll
    for (int h = 0; h < 16; h++) acc[h] = 0.f;
#pragma unroll
    for (int kk = 0; kk < 8; kk++) {
        const float4* wr = (const float4*)(Wg + (size_t)(t*8 + kk)*16);
        float4 w0 = wr[0], w1 = wr[1], w2 = wr[2], w3 = wr[3];
        float v = xv[kk];
        acc[0]+=v*w0.x; acc[1]+=v*w0.y; acc[2]+=v*w0.z; acc[3]+=v*w0.w;
        acc[4]+=v*w1.x; acc[5]+=v*w1.y; acc[6]+=v*w1.z; acc[7]+=v*w1.w;
        acc[8]+=v*w2.x; acc[9]+=v*w2.y; acc[10]+=v*w2.z; acc[11]+=v*w2.w;
        acc[12]+=v*w3.x; acc[13]+=v*w3.y; acc[14]+=v*w3.z; acc[15]+=v*w3.w;
    }
#pragma unroll
    for (int h = 0; h < 16; h++) {
#pragma unroll
        for (int o = 16; o >= 1; o >>= 1)
            acc[h] += __shfl_xor_sync(0xffffffffu, acc[h], o);
    }
    if (lane == 0) {
#pragma unroll
        for (int h = 0; h < 16; h++) red[w][h] = acc[h];
    }
    __syncthreads();
    if (t < 16) {
        float s = red[0][t] + red[1][t] + red[2][t] + red[3][t] + bg[t] + aw[t];
        modv[(size_t)row*16 + t] = 1.f / (1.f + __expf(-s));
    }
}

// ======================= tcgen05 tf32 GEMM ====================================
#define GTN 256
#define GBUF 98304
#define GSMEM (2048 + 1024 + 2*GBUF)

__global__ __launch_bounds__(128, 1)
void tf32_gemm(const float* __restrict__ A, const float* __restrict__ Bt,
               const float* __restrict__ bias, const float* __restrict__ Cold,
               float* __restrict__ C, int M, int N, int K, float alpha, float beta)
{
#if HAS_TCGEN05
    extern __shared__ char smraw[];
    uint32_t smb = smem_u32(smraw);
    uint32_t ctrl = smb;
    uint32_t tiles_u = (smb + 2048 + 1023) & ~1023u;
    char* tiles_p = smraw + (tiles_u - smb);
    float* sbias = (float*)(smraw + 64);
    const int tid = threadIdx.x;
    const int lane = tid & 31, wid = tid >> 5;
    const int nbase = blockIdx.x * GTN, mbase = blockIdx.y * 128;

    if (tid == 0) { MBARRIER_INIT(ctrl + 0, 1); MBARRIER_INIT(ctrl + 8, 1); }
    if (wid == 0) {
        TCGEN05_ALLOC(ctrl + 16, 256);
        TCGEN05_RELINQUISH();
    }
    sbias[tid]       = bias[nbase + tid];
    sbias[tid + 128] = bias[nbase + tid + 128];
    __syncthreads();
    uint32_t tmem;
    asm volatile("ld.shared.b32 %0, [%1];" : "=r"(tmem) : "r"(ctrl + 16));

    const float* arow  = A  + (size_t)(mbase + tid) * K;
    const float* brow0 = Bt + (size_t)(nbase + tid) * K;
    const float* brow1 = Bt + (size_t)(nbase + tid + 128) * K;
    const uint32_t xr = (uint32_t)(tid & 7) << 4;
    const uint32_t arb = (uint32_t)tid * 128;
    const uint32_t brb0 = (uint32_t)tid * 128;
    const uint32_t brb1 = (uint32_t)(tid + 128) * 128;

    int ph0 = 0, ph1 = 0;
    const uint32_t idesc = (1u<<4) | (2u<<7) | (2u<<10) | ((GTN/8)<<17) | (8u<<24);
    const int nsteps = K / 32;
    for (int s = 0; s < nsteps; s++) {
        int buf = s & 1;
        if (s >= 2) {
            if (buf == 0) { MBARRIER_WAIT_PARITY(ctrl + 0, ph0); ph0 ^= 1; }
            else          { MBARRIER_WAIT_PARITY(ctrl + 8, ph1); ph1 ^= 1; }
        }
        char* tb = tiles_p + buf * GBUF;
        const float4* ap  = (const float4*)(arow  + s*32);
        const float4* bp0 = (const float4*)(brow0 + s*32);
        const float4* bp1 = (const float4*)(brow1 + s*32);
#pragma unroll
        for (int c = 0; c < 8; c++) {
            uint32_t sw = ((uint32_t)(c * 16)) ^ xr;
            uint4 hi, lo;
            float4 v = ap[c];
            split4(v, hi, lo);
            *(uint4*)(tb + arb + sw)          = hi;
            *(uint4*)(tb + 16384 + arb + sw)  = lo;
            v = bp0[c];
            split4(v, hi, lo);
            *(uint4*)(tb + 32768 + brb0 + sw) = hi;
            *(uint4*)(tb + 65536 + brb0 + sw) = lo;
            v = bp1[c];
            split4(v, hi, lo);
            *(uint4*)(tb + 32768 + brb1 + sw) = hi;
            *(uint4*)(tb + 65536 + brb1 + sw) = lo;
        }
        asm volatile("fence.proxy.async.shared::cta;" ::: "memory");
        __syncthreads();
        if (wid == 0) {
            if (elect_one_pred()) {
                uint32_t base = tiles_u + buf * GBUF;
                uint64_t dAh = MAKE_SMEM_DESC(base);
                uint64_t dAl = MAKE_SMEM_DESC(base + 16384);
                uint64_t dBh = MAKE_SMEM_DESC(base + 32768);
                uint64_t dBl = MAKE_SMEM_DESC(base + 65536);
#pragma unroll
                for (int sub = 0; sub < 4; sub++)
                    mma_tf32_ss(tmem, dAh + sub*2, dBh + sub*2, idesc, !(s == 0 && sub == 0));
#pragma unroll
                for (int sub = 0; sub < 4; sub++)
                    mma_tf32_ss(tmem, dAh + sub*2, dBl + sub*2, idesc, true);
#pragma unroll
                for (int sub = 0; sub < 4; sub++)
                    mma_tf32_ss(tmem, dAl + sub*2, dBh + sub*2, idesc, true);
                TCGEN05_COMMIT(ctrl + buf * 8);
            }
        }
    }
    MBARRIER_WAIT_PARITY(ctrl + 0, ph0);
    MBARRIER_WAIT_PARITY(ctrl + 8, ph1);
    TCGEN05_FENCE_AFTER();

    const int row = mbase + wid*32 + lane;
#pragma unroll 1
    for (int cc = 0; cc < 8; cc++) {
        uint32_t d[32];
        TCGEN05_LD_32X32B_X32(d, tmem + cc*32);
        TCGEN05_WAIT_LD();
        const int col = nbase + cc*32;
        float* cp = C + (size_t)row * N + col;
        const float* oldp = Cold + (size_t)row * N + col;
#pragma unroll
        for (int j = 0; j < 32; j += 4) {
            float4 o;
            o.x = alpha * (__uint_as_float(d[j+0]) + sbias[cc*32 + j + 0]);
            o.y = alpha * (__uint_as_float(d[j+1]) + sbias[cc*32 + j + 1]);
            o.z = alpha * (__uint_as_float(d[j+2]) + sbias[cc*32 + j + 2]);
            o.w = alpha * (__uint_as_float(d[j+3]) + sbias[cc*32 + j + 3]);
            if (beta != 0.f) {
                float4 ov = *(const float4*)(oldp + j);
                o.x += beta*ov.x; o.y += beta*ov.y; o.z += beta*ov.z; o.w += beta*ov.w;
            }
            *(float4*)(cp + j) = o;
        }
    }
    TCGEN05_FENCE_BEFORE();
    __syncthreads();
    if (tid == 0) {
        asm volatile("mbarrier.inval.shared.b64 [%0];" :: "r"(ctrl + 0) : "memory");
        asm volatile("mbarrier.inval.shared.b64 [%0];" :: "r"(ctrl + 8) : "memory");
    }
    __syncthreads();
    if (wid == 0) TCGEN05_DEALLOC(tmem, 256);
#else
    const int tid = threadIdx.x;
    const int nbase = blockIdx.x * GTN, mbase = blockIdx.y * 128;
    const int row = mbase + tid;
    const float* arow = A + (size_t)row * K;
    for (int n = 0; n < GTN; n++) {
        const float* brow = Bt + (size_t)(nbase + n) * K;
        float s = 0.f;
        for (int k = 0; k < K; k++) s += arow[k] * brow[k];
        float o = alpha * (s + bias[nbase + n]);
        if (beta != 0.f) o += beta * Cold[(size_t)row * N + nbase + n];
        C[(size_t)row * N + nbase + n] = o;
    }
#endif
}

// ======================= tcgen05 flash attention, main (hd=64) ================
#define FMA_Q 2048
#define FMA_K (2048 + 32768)
#define FMA_V (2048 + 65536)
#define FMA_SMEM (2048 + 98304 + 1024)

__global__ __launch_bounds__(256, 1)
void flash_main_tc(const float* __restrict__ Q, const float* __restrict__ K,
                   const float* __restrict__ V, const float* __restrict__ modv,
                   const int* __restrict__ mask, float* __restrict__ O)
{
#if HAS_TCGEN05
    extern __shared__ char smraw[];
    uint32_t smb = smem_u32(smraw);
    uint32_t base = (smb + 1023) & ~1023u;
    char* bp = smraw + (base - smb);
    float* l2  = (float*)(bp + 32);      // 256 floats
    float* mbf = (float*)(bp + 1056);    // 128 floats
    const int tid = threadIdx.x;
    const int lane = tid & 31, wid = tid >> 5;
    const int qt = blockIdx.x, h = blockIdx.y, b = blockIdx.z;
    const int qrow0 = b*SS + qt*128;
    const int rowm = (wid & 3)*32 + lane;
    const int colhalf = wid >> 2;

    if (tid == 0) { MBARRIER_INIT(base + 0, 1); MBARRIER_INIT(base + 8, 1); }
    if (wid == 0) { TCGEN05_ALLOC(base + 16, 256); TCGEN05_RELINQUISH(); }

    {
        const float* qg = Q + (size_t)qrow0*HH + h*64;
        int r = tid >> 1, d0 = (tid & 1)*32;
#pragma unroll
        for (int i = 0; i < 8; i++) {
            float4 v = *(const float4*)(qg + (size_t)r*HH + d0 + i*4);
            char* qb = bp + FMA_Q;
            *(uint32_t*)(qb + kmaj_off(r, d0+i*4+0, 128)) = f2tf32(v.x);
            *(uint32_t*)(qb + kmaj_off(r, d0+i*4+1, 128)) = f2tf32(v.y);
            *(uint32_t*)(qb + kmaj_off(r, d0+i*4+2, 128)) = f2tf32(v.z);
            *(uint32_t*)(qb + kmaj_off(r, d0+i*4+3, 128)) = f2tf32(v.w);
        }
    }
    float mrow = modv[(size_t)(qrow0 + rowm)*NH + h] * 0.125f;
    float lsum = 0.f;
    __syncthreads();
    uint32_t tmem;
    asm volatile("ld.shared.b32 %0, [%1];" : "=r"(tmem) : "r"(base + 16));
    const uint32_t tS = tmem, tO = tmem + 128;
    const uint32_t stoff = (uint32_t)(wid & 3) << 21;
    const uint64_t qdesc = MAKE_SMEM_DESC(base + FMA_Q);
    const uint64_t kdesc = MAKE_SMEM_DESC(base + FMA_K);
    const uint64_t vdesc = MAKE_SMEM_DESC(base + FMA_V);
    const uint32_t idQK = (1u<<4)|(2u<<7)|(2u<<10)|(16u<<17)|(8u<<24);  // N=128,M=128
    const uint32_t idPV = (1u<<4)|(2u<<7)|(2u<<10)|(8u<<17)|(8u<<24);   // N=64, M=128

    int ph0 = 0, ph1 = 0;
#pragma unroll 1
    for (int kt = 0; kt < SS/128; kt++) {
        if (kt > 0) { MBARRIER_WAIT_PARITY(base + 8, ph1); ph1 ^= 1; }
        const int krow0 = b*SS + kt*128;
        const float* kg = K + (size_t)krow0*HH + h*64;
        const float* vg = V + (size_t)krow0*HH + h*64;
        {
            int r = tid >> 1, d0 = (tid & 1)*32;
            char* kb = bp + FMA_K;
            char* vb = bp + FMA_V;
#pragma unroll
            for (int i = 0; i < 8; i++) {
                float4 kv = *(const float4*)(kg + (size_t)r*HH + d0 + i*4);
                *(uint32_t*)(kb + kmaj_off(r, d0+i*4+0, 128)) = f2tf32(kv.x);
                *(uint32_t*)(kb + kmaj_off(r, d0+i*4+1, 128)) = f2tf32(kv.y);
                *(uint32_t*)(kb + kmaj_off(r, d0+i*4+2, 128)) = f2tf32(kv.z);
                *(uint32_t*)(kb + kmaj_off(r, d0+i*4+3, 128)) = f2tf32(kv.w);
                float4 vv = *(const float4*)(vg + (size_t)r*HH + d0 + i*4);
                *(uint32_t*)(vb + kmaj_off(d0+i*4+0, r, 64)) = f2tf32(vv.x);
                *(uint32_t*)(vb + kmaj_off(d0+i*4+1, r, 64)) = f2tf32(vv.y);
                *(uint32_t*)(vb + kmaj_off(d0+i*4+2, r, 64)) = f2tf32(vv.z);
                *(uint32_t*)(vb + kmaj_off(d0+i*4+3, r, 64)) = f2tf32(vv.w);
            }
            if (tid < 128) mbf[tid] = mask[krow0 + tid] ? 0.f : -1e30f;
        }
        asm volatile("fence.proxy.async.shared::cta;" ::: "memory");
        __syncthreads();
        if (wid == 0 && elect_one_pred()) {
#pragma unroll
            for (int s = 0; s < 8; s++)
                mma_tf32_ss(tS, qdesc + (s>>2)*1024 + (s&3)*2,
                            kdesc + (s>>2)*1024 + (s&3)*2, idQK, s > 0);
            TCGEN05_COMMIT(base + 0);
        }
        MBARRIER_WAIT_PARITY(base + 0, ph0); ph0 ^= 1;
        TCGEN05_FENCE_AFTER();
#pragma unroll
        for (int c = 0; c < 2; c++) {
            uint32_t col0 = colhalf*64 + c*32;
            uint32_t r[32];
            TCGEN05_LD_32X32B_X32(r, tS + col0);
            TCGEN05_WAIT_LD();
#pragma unroll
            for (int j = 0; j < 32; j++) {
                float s = __uint_as_float(r[j]) * mrow + mbf[col0 + j];
                float e = __expf(s);
                lsum += e;
                r[j] = f2tf32(e);
            }
            TCGEN05_ST_32X32B_X32(tS + col0 + stoff, r);
        }
        TCGEN05_WAIT_ST();
        TCGEN05_FENCE_BEFORE();
        __syncthreads();
        if (wid == 0 && elect_one_pred()) {
            TCGEN05_FENCE_AFTER();
#pragma unroll
            for (int s = 0; s < 16; s++)
                mma_tf32_ts(tO, tS + s*8,
                            vdesc + (s>>2)*512 + (s&3)*2, idPV, kt > 0 || s > 0);
            TCGEN05_COMMIT(base + 8);
        }
    }
    MBARRIER_WAIT_PARITY(base + 8, ph1); ph1 ^= 1;
    TCGEN05_FENCE_AFTER();

    uint32_t r[32];
    TCGEN05_LD_32X32B_X32(r, tO + colhalf*32);
    TCGEN05_WAIT_LD();
    l2[colhalf*128 + rowm] = lsum;
    __syncthreads();
    float linv = 1.f / (l2[rowm] + l2[128 + rowm]);
    float* og = O + (size_t)(qrow0 + rowm)*HH + h*64 + colhalf*32;
#pragma unroll
    for (int j = 0; j < 32; j += 4) {
        *(float4*)(og + j) = make_float4(
            __uint_as_float(r[j+0])*linv, __uint_as_float(r[j+1])*linv,
            __uint_as_float(r[j+2])*linv, __uint_as_float(r[j+3])*linv);
    }
    TCGEN05_FENCE_BEFORE();
    __syncthreads();
    if (tid == 0) {
        asm volatile("mbarrier.inval.shared.b64 [%0];" :: "r"(base + 0) : "memory");
        asm volatile("mbarrier.inval.shared.b64 [%0];" :: "r"(base + 8) : "memory");
    }
    __syncthreads();
    if (wid == 0) TCGEN05_DEALLOC(tmem, 256);
#else
    const int tid = threadIdx.x;
    const int qt = blockIdx.x, h = blockIdx.y, b = blockIdx.z;
    const int qrow0 = b*SS + qt*128;
    int rl = tid >> 1, half = tid & 1;
    int row = qrow0 + rl;
    float mrow = modv[(size_t)row*NH + h] * 0.125f;
    float o[32]; for (int j = 0; j < 32; j++) o[j] = 0.f;
    float l = 0.f;
    for (int n = 0; n < SS; n++) {
        int kr = b*SS + n;
        float s = 0.f;
        for (int d = 0; d < 64; d++)
            s += Q[(size_t)row*HH + h*64 + d] * K[(size_t)kr*HH + h*64 + d];
        s = s*mrow + (mask[kr] ? 0.f : -1e30f);
        float e = __expf(s);
        l += e;
        for (int j = 0; j < 32; j++)
            o[j] += e * V[(size_t)kr*HH + h*64 + half*32 + j];
    }
    for (int j = 0; j < 32; j++)
        O[(size_t)row*HH + h*64 + half*32 + j] = o[j] / l;
#endif
}

// ======================= tcgen05 flash attention, branch (hd=256) =============
#define FBR_Q 2048
#define FBR_K (2048 + 131072)
#define FBR_V (2048 + 163840)
#define FBR_SMEM (2048 + 196608 + 1024)

__global__ __launch_bounds__(256, 1)
void flash_branch_tc(const float* __restrict__ QKV, float* __restrict__ O, float scale)
{
#if HAS_TCGEN05
    extern __shared__ char smraw[];
    uint32_t smb = smem_u32(smraw);
    uint32_t base = (smb + 1023) & ~1023u;
    char* bp = smraw + (base - smb);
    float* l2 = (float*)(bp + 32);
    const int tid = threadIdx.x;
    const int lane = tid & 31, wid = tid >> 5;
    const int qt = blockIdx.x, h = blockIdx.y, b = blockIdx.z;
    const int qrow0 = b*SS + qt*128;
    const int rowm = (wid & 3)*32 + lane;
    const int colhalf = wid >> 2;

    if (tid == 0) { MBARRIER_INIT(base + 0, 1); MBARRIER_INIT(base + 8, 1); }
    if (wid == 0) { TCGEN05_ALLOC(base + 16, 512); TCGEN05_RELINQUISH(); }

    {
        const float* qg = QKV + (size_t)qrow0*H3 + h*256;
        int r = tid >> 1, d0 = (tid & 1)*128;
        char* qb = bp + FBR_Q;
#pragma unroll 4
        for (int i = 0; i < 32; i++) {
            float4 v = *(const float4*)(qg + (size_t)r*H3 + d0 + i*4);
            *(uint32_t*)(qb + kmaj_off(r, d0+i*4+0, 128)) = f2tf32(v.x);
            *(uint32_t*)(qb + kmaj_off(r, d0+i*4+1, 128)) = f2tf32(v.y);
            *(uint32_t*)(qb + kmaj_off(r, d0+i*4+2, 128)) = f2tf32(v.z);
            *(uint32_t*)(qb + kmaj_off(r, d0+i*4+3, 128)) = f2tf32(v.w);
        }
    }
    float lsum = 0.f;
    __syncthreads();
    uint32_t tmem;
    asm volatile("ld.shared.b32 %0, [%1];" : "=r"(tmem) : "r"(base + 16));
    const uint32_t tS = tmem, tO = tmem + 128;
    const uint32_t stoff = (uint32_t)(wid & 3) << 21;
    const uint64_t qdesc = MAKE_SMEM_DESC(base + FBR_Q);
    const uint64_t kdesc = MAKE_SMEM_DESC(base + FBR_K);
    const uint64_t vdesc = MAKE_SMEM_DESC(base + FBR_V);
    const uint32_t idQK = (1u<<4)|(2u<<7)|(2u<<10)|(16u<<17)|(8u<<24);
    const uint32_t idPV = (1u<<4)|(2u<<7)|(2u<<10)|(8u<<17)|(8u<<24);

    int ph0 = 0, ph1 = 0;
#pragma unroll 1
    for (int kt = 0; kt < SS/128; kt++) {
        if (kt > 0) { MBARRIER_WAIT_PARITY(base + 8, ph1); ph1 ^= 1; }
        const int krow0 = b*SS + kt*128;
        // ---- QK over 4 d-chunks ----
#pragma unroll 1
        for (int dc = 0; dc < 4; dc++) {
            if (dc > 0) { MBARRIER_WAIT_PARITY(base + 0, ph0); ph0 ^= 1; }
            const float* kg = QKV + (size_t)krow0*H3 + HH + h*256 + dc*64;
            int r = tid >> 1, d0 = (tid & 1)*32;
            char* kb = bp + FBR_K;
#pragma unroll
            for (int i = 0; i < 8; i++) {
                float4 v = *(const float4*)(kg + (size_t)r*H3 + d0 + i*4);
                *(uint32_t*)(kb + kmaj_off(r, d0+i*4+0, 128)) = f2tf32(v.x);
                *(uint32_t*)(kb + kmaj_off(r, d0+i*4+1, 128)) = f2tf32(v.y);
                *(uint32_t*)(kb + kmaj_off(r, d0+i*4+2, 128)) = f2tf32(v.z);
                *(uint32_t*)(kb + kmaj_off(r, d0+i*4+3, 128)) = f2tf32(v.w);
            }
            asm volatile("fence.proxy.async.shared::cta;" ::: "memory");
            __syncthreads();
            if (wid == 0 && elect_one_pred()) {
#pragma unroll
                for (int j = 0; j < 8; j++)
                    mma_tf32_ss(tS, qdesc + (dc*2 + (j>>2))*1024 + (j&3)*2,
                                kdesc + (j>>2)*1024 + (j&3)*2, idQK,
                                !(dc == 0 && j == 0));
                TCGEN05_COMMIT(base + 0);
            }
        }
        MBARRIER_WAIT_PARITY(base + 0, ph0); ph0 ^= 1;
        TCGEN05_FENCE_AFTER();
        // ---- softmax ----
#pragma unroll
        for (int c = 0; c < 2; c++) {
            uint32_t col0 = colhalf*64 + c*32;
            uint32_t r[32];
            TCGEN05_LD_32X32B_X32(r, tS + col0);
            TCGEN05_WAIT_LD();
#pragma unroll
            for (int j = 0; j < 32; j++) {
                float e = __expf(__uint_as_float(r[j]) * scale);
                lsum += e;
                r[j] = f2tf32(e);
            }
            TCGEN05_ST_32X32B_X32(tS + col0 + stoff, r);
        }
        TCGEN05_WAIT_ST();
        TCGEN05_FENCE_BEFORE();
        __syncthreads();
        // ---- PV over 4 d-chunks ----
#pragma unroll 1
        for (int dc = 0; dc < 4; dc++) {
            if (dc > 0) { MBARRIER_WAIT_PARITY(base + 8, ph1); ph1 ^= 1; }
            const float* vg = QKV + (size_t)krow0*H3 + 2*HH + h*256 + dc*64;
            int r = tid >> 1, d0 = (tid & 1)*32;
            char* vb = bp + FBR_V;
#pragma unroll
            for (int i = 0; i < 8; i++) {
                float4 v = *(const float4*)(vg + (size_t)r*H3 + d0 + i*4);
                *(uint32_t*)(vb + kmaj_off(d0+i*4+0, r, 64)) = f2tf32(v.x);
                *(uint32_t*)(vb + kmaj_off(d0+i*4+1, r, 64)) = f2tf32(v.y);
                *(uint32_t*)(vb + kmaj_off(d0+i*4+2, r, 64)) = f2tf32(v.z);
                *(uint32_t*)(vb + kmaj_off(d0+i*4+3, r, 64)) = f2tf32(v.w);
            }
            asm volatile("fence.proxy.async.shared::cta;" ::: "memory");
            __syncthreads();
            if (wid == 0 && elect_one_pred()) {
                TCGEN05_FENCE_AFTER();
#pragma unroll
                for (int s = 0; s < 16; s++)
                    mma_tf32_ts(tO + dc*64, tS + s*8,
                                vdesc + (s>>2)*512 + (s&3)*2, idPV,
                                kt > 0 || s > 0);   // FIX: accumulate across K-steps
                TCGEN05_COMMIT(base + 8);
            }
        }
    }
    MBARRIER_WAIT_PARITY(base + 8, ph1); ph1 ^= 1;
    TCGEN05_FENCE_AFTER();

    // FIX: full epilogue coverage — each warp handles 4 column blocks
    l2[colhalf*128 + rowm] = lsum;
    float* ogbase = O + (size_t)(qrow0 + rowm)*HH + h*256;
#pragma unroll 1
    for (int c = 0; c < 4; c++) {
        uint32_t r[32];
        TCGEN05_LD_32X32B_X32(r, tO + colhalf*128 + c*32);
        TCGEN05_WAIT_LD();
        if (c == 0) __syncthreads();   // l2 visible before first use
        float linv = 1.f / (l2[rowm] + l2[128 + rowm]);
        float* og = ogbase + colhalf*128 + c*32;
#pragma unroll
        for (int j = 0; j < 32; j += 4) {
            *(float4*)(og + j) = make_float4(
                __uint_as_float(r[j+0])*linv, __uint_as_float(r[j+1])*linv,
                __uint_as_float(r[j+2])*linv, __uint_as_float(r[j+3])*linv);
        }
    }
    TCGEN05_FENCE_BEFORE();
    __syncthreads();
    if (tid == 0) {
        asm volatile("mbarrier.inval.shared.b64 [%0];" :: "r"(base + 0) : "memory");
        asm volatile("mbarrier.inval.shared.b64 [%0];" :: "r"(base + 8) : "memory");
    }
    __syncthreads();
    if (wid == 0) TCGEN05_DEALLOC(tmem, 512);
#else
    const int tid = threadIdx.x;
    const int qt = blockIdx.x, h = blockIdx.y, b = blockIdx.z;
    const int qrow0 = b*SS + qt*128;
    int rl = tid >> 1, half = tid & 1;
    int row = qrow0 + rl;
    const float* qg = QKV + (size_t)row*H3 + h*256;
    float o[128]; for (int j = 0; j < 128; j++) o[j] = 0.f;
    float l = 0.f;
    for (int n = 0; n < SS; n++) {
        int kr = b*SS + n;
        const float* kg = QKV + (size_t)kr*H3 + HH + h*256;
        const float* vg = QKV + (size_t)kr*H3 + 2*HH + h*256 + half*128;
        float s = 0.f;
        for (int d = 0; d < 256; d++) s += qg[d] * kg[d];
        float e = __expf(s * scale);
        l += e;
        for (int j = 0; j < 128; j++) o[j] += e * vg[j];
    }
    for (int j = 0; j < 128; j++)
        O[(size_t)row*HH + h*256 + half*128 + j] = o[j] / l;
#endif
}

// ------------------------ host launch -----------------------------------------
extern "C" void kernel_launch(void* const* d_in, const int* in_sizes, int n_in,
                              void* d_out, int out_size) {
    const float* X        = (const float*)d_in[0];
    const int*   msk      = (const int*)  d_in[1];
    const float* cv       = (const float*)d_in[2];
    const float* Wq       = (const float*)d_in[3];
    const float* bq       = (const float*)d_in[4];
    const float* Wk       = (const float*)d_in[5];
    const float* bk       = (const float*)d_in[6];
    const float* Wv       = (const float*)d_in[7];
    const float* bv       = (const float*)d_in[8];
    const float* Wg       = (const float*)d_in[9];
    const float* bg       = (const float*)d_in[10];
    const float* Wa       = (const float*)d_in[11];
    const float* ba       = (const float*)d_in[12];
    const float* ca_in_w  = (const float*)d_in[13];
    const float* ca_in_b  = (const float*)d_in[14];
    const float* ca_out_w = (const float*)d_in[15];
    const float* ca_out_b = (const float*)d_in[16];
    const float* ma_in_w  = (const float*)d_in[17];
    const float* ma_in_b  = (const float*)d_in[18];
    const float* ma_out_w = (const float*)d_in[19];
    const float* ma_out_b = (const float*)d_in[20];
    const float* Wo       = (const float*)d_in[21];
    const float* bo       = (const float*)d_in[22];
    float* out = (float*)d_out;

    float *q, *k, *v, *ctx, *bctx, *qkv, *modv, *aw;
    float *wtq, *wtk, *wtv, *wtci, *wtco, *wtmi, *wtmo, *wto;
    cudaGetSymbolAddress((void**)&q,    g_q);
    cudaGetSymbolAddress((void**)&k,    g_k);
    cudaGetSymbolAddress((void**)&v,    g_v);
    cudaGetSymbolAddress((void**)&ctx,  g_ctx);
    cudaGetSymbolAddress((void**)&bctx, g_bctx);
    cudaGetSymbolAddress((void**)&qkv,  g_qkv);
    cudaGetSymbolAddress((void**)&modv, g_mod);
    cudaGetSymbolAddress((void**)&aw,   g_aw);
    cudaGetSymbolAddress((void**)&wtq,  g_wtq);
    cudaGetSymbolAddress((void**)&wtk,  g_wtk);
    cudaGetSymbolAddress((void**)&wtv,  g_wtv);
    cudaGetSymbolAddress((void**)&wtci, g_wtci);
    cudaGetSymbolAddress((void**)&wtco, g_wtco);
    cudaGetSymbolAddress((void**)&wtmi, g_wtmi);
    cudaGetSymbolAddress((void**)&wtmo, g_wtmo);
    cudaGetSymbolAddress((void**)&wto,  g_wto);

    cudaFuncSetAttribute(tf32_gemm,
                         cudaFuncAttributeMaxDynamicSharedMemorySize, GSMEM);
    cudaFuncSetAttribute(flash_main_tc,
                         cudaFuncAttributeMaxDynamicSharedMemorySize, FMA_SMEM);
    cudaFuncSetAttribute(flash_branch_tc,
                         cudaFuncAttributeMaxDynamicSharedMemorySize, FBR_SMEM);

    dim3 tb(32, 8);
    transpose_w<<<dim3(HH/32, HH/32), tb>>>(Wq, wtq, HH, HH);
    transpose_w<<<dim3(HH/32, HH/32), tb>>>(Wk, wtk, HH, HH);
    transpose_w<<<dim3(HH/32, HH/32), tb>>>(Wv, wtv, HH, HH);
    transpose_w<<<dim3(H3/32, HH/32), tb>>>(ca_in_w, wtci, HH, H3);
    transpose_w<<<dim3(HH/32, HH/32), tb>>>(ca_out_w, wtco, HH, HH);
    transpose_w<<<dim3(H3/32, HH/32), tb>>>(ma_in_w, wtmi, HH, H3);
    transpose_w<<<dim3(HH/32, HH/32), tb>>>(ma_out_w, wtmo, HH, HH);
    transpose_w<<<dim3(HH/32, HH/32), tb>>>(Wo, wto, HH, HH);

    awareness_kernel<<<1, 32>>>(cv, Wa, ba, aw);
    modulation2<<<NROWS, 128>>>(X, Wg, bg, aw, modv);

    dim3 gN(HH/GTN, NROWS/128);   // (4, 32)
    dim3 g3(H3/GTN, NROWS/128);   // (12, 32)

    tf32_gemm<<<gN, 128, GSMEM>>>(X, wtq, bq, nullptr, q, NROWS, HH, HH, 1.f, 0.f);
    tf32_gemm<<<gN, 128, GSMEM>>>(X, wtk, bk, nullptr, k, NROWS, HH, HH, 1.f, 0.f);
    tf32_gemm<<<gN, 128, GSMEM>>>(X, wtv, bv, nullptr, v, NROWS, HH, HH, 1.f, 0.f);

    flash_main_tc<<<dim3(SS/128, NH, BB), 256, FMA_SMEM>>>(q, k, v, modv, msk, ctx);

    tf32_gemm<<<g3, 128, GSMEM>>>(X, wtci, ca_in_b, nullptr, qkv, NROWS, H3, HH, 1.f, 0.f);
    flash_branch_tc<<<dim3(SS/128, 4, BB), 256, FBR_SMEM>>>(qkv, bctx, 0.0625f);
    tf32_gemm<<<gN, 128, GSMEM>>>(bctx, wtco, ca_out_b, ctx, ctx, NROWS, HH, HH, 0.7f, 0.3f);

    tf32_gemm<<<g3, 128, GSMEM>>>(ctx, wtmi, ma_in_b, nullptr, qkv, NROWS, H3, HH, 1.f, 0.f);
    flash_branch_tc<<<dim3(SS/128, 4, BB), 256, FBR_SMEM>>>(qkv, bctx, 0.0625f);
    tf32_gemm<<<gN, 128, GSMEM>>>(bctx, wtmo, ma_out_b, ctx, ctx, NROWS, HH, HH, 0.15f, 0.85f);

    tf32_gemm<<<gN, 128, GSMEM>>>(ctx, wto, bo, nullptr, out, NROWS, HH, HH, 1.f, 0.f);
}